// round 13
// baseline (speedup 1.0000x reference)
#include <cuda_runtime.h>
#include <cuda_fp16.h>
#include <math.h>
#include <stdint.h>

#define NN    50000
#define NE    300000
#define INDIM 2000
#define DF    128
#define H1D   256
#define H2D   128
#define ODIM  32
#define KD    4
#define KPAD1 2048
#define MP1   50048                 // gemm1 rows padded to tile (391*128)

// ---------------- scratch (static device globals; no allocation) ----------------
static __device__ __half d_h0[NN * DF];
static __device__ __half d_h1[NN * H1D];
static __device__ __half d_z1[KD * NN * H1D];
static __device__ __half d_h2[KD * NN * H2D];
static __device__ __half d_h0p[2 * MP1 * DF];    // split-K fp16 partials (25.6 MB)
static __device__ float  d_pqf[NN * 16];
static __device__ __half d_WhT[DF * KPAD1];
static __device__ __half d_g1T[H1D * DF];
static __device__ __half d_g2T[H2D * H1D];
static __device__ float d_deg[KD * NN];
static __device__ float d_dinv[KD * NN];
static __device__ float d_norm[KD * NE];
static __device__ int   d_rowptr[NN + 1];
static __device__ int   d_fill[NN];
static __device__ int   d_ssrc[NE];
static __device__ int   d_bsum[64];
static __device__ float d_maccP[32][KD * H2D];
static __device__ float d_macc[KD * H2D];

__device__ __forceinline__ uint32_t h2u(__half2 h) { return *reinterpret_cast<uint32_t*>(&h); }

__device__ __forceinline__ uint32_t smem_u32(const void* p) {
    uint32_t a;
    asm("{ .reg .u64 t; cvta.to.shared.u64 t, %1; cvt.u32.u64 %0, t; }" : "=r"(a) : "l"(p));
    return a;
}
__device__ __forceinline__ void cp_async16(uint32_t saddr, const void* gaddr, uint32_t ssize) {
    asm volatile("cp.async.cg.shared.global [%0], [%1], 16, %2;"
                 :: "r"(saddr), "l"(gaddr), "r"(ssize) : "memory");
}
#define CP_COMMIT() asm volatile("cp.async.commit_group;" ::: "memory")
template <int N>
__device__ __forceinline__ void cp_wait() {
    asm volatile("cp.async.wait_group %0;" :: "n"(N) : "memory");
}
__device__ __forceinline__ void ldmx4(uint32_t* r, uint32_t addr) {
    asm volatile("ldmatrix.sync.aligned.m8n8.x4.shared.b16 {%0,%1,%2,%3}, [%4];"
                 : "=r"(r[0]), "=r"(r[1]), "=r"(r[2]), "=r"(r[3]) : "r"(addr));
}
__device__ __forceinline__ void mma16816(float* d, const uint32_t* a, const uint32_t* b) {
    asm volatile("mma.sync.aligned.m16n8k16.row.col.f32.f16.f16.f32 "
                 "{%0,%1,%2,%3}, {%4,%5,%6,%7}, {%8,%9}, {%0,%1,%2,%3};"
                 : "+f"(d[0]), "+f"(d[1]), "+f"(d[2]), "+f"(d[3])
                 : "r"(a[0]), "r"(a[1]), "r"(a[2]), "r"(a[3]), "r"(b[0]), "r"(b[1]));
}

// ---------------- persistent HMMA GEMM, unified fp16 smem + ldmatrix ------------------
// Block tile 128x128, BK=32, 8 warps (4m x 2n), NS=4 stages (82KB, 2 CTAs/SM).
// AF32: A fp32 in gmem, converted at copy (LDG+cvt+STS); split-K fp16 partials to Cp.
template <bool AF32, int NS>
__global__ void __launch_bounds__(256, 2) gemm_pipe(const void* __restrict__ Ain,
                                                    const __half* __restrict__ Bt,
                                                    __half* __restrict__ C,
                                                    __half* __restrict__ Cp,
                                                    int M, int Kreal, int KB, int Ntot,
                                                    int NC, int ntm, int ntn, int nsplit) {
    extern __shared__ char sm[];
    const int ASTAGE = 128 * 80;
    const int BSTAGE = 128 * 80;
    char* Abase = sm;
    char* Bbase = sm + NS * ASTAGE;

    const int tid = threadIdx.x, lane = tid & 31, w = tid >> 5;
    const int wm = w & 3, wn = w >> 2;
    const int g = lane >> 2, tg = lane & 3;
    const int lr = lane & 7, grp = lane >> 3;
    const int nmn = ntm * ntn;
    const int ntiles = nmn * nsplit;
    const int MPAD = ntm * 128;

    const int arow = tid >> 1;
    const int acol = (tid & 1) * 16;

    for (int tile = blockIdx.x; tile < ntiles; tile += gridDim.x) {
        const int tmn = tile % nmn;
        const int kh  = tile / nmn;
        const int m0 = (tmn % ntm) * 128;
        const int n0 = (tmn / ntm) * 128;
        const int kc0 = kh * NC;

        __syncthreads();

        float acc[2][8][4];
#pragma unroll
        for (int i = 0; i < 2; i++)
#pragma unroll
            for (int j = 0; j < 8; j++)
#pragma unroll
                for (int q = 0; q < 4; q++) acc[i][j][q] = 0.0f;

        float4 rf[4];

        auto ldgA = [&](int gc) {
            const float* A = (const float*)Ain;
            int gr = m0 + arow;
            bool rok = gr < M;
            int grc = rok ? gr : 0;
            const float* base = A + (size_t)grc * Kreal + gc * 32 + acol;
#pragma unroll
            for (int q = 0; q < 4; q++) {
                int col = gc * 32 + acol + q * 4;
                rf[q] = (rok && col < Kreal) ? *(const float4*)(base + q * 4)
                                             : make_float4(0.f, 0.f, 0.f, 0.f);
            }
        };
        auto stsA = [&](int stage) {
            char* As = Abase + stage * ASTAGE;
            uint32_t r0 = h2u(__floats2half2_rn(rf[0].x, rf[0].y));
            uint32_t r1 = h2u(__floats2half2_rn(rf[0].z, rf[0].w));
            uint32_t r2 = h2u(__floats2half2_rn(rf[1].x, rf[1].y));
            uint32_t r3 = h2u(__floats2half2_rn(rf[1].z, rf[1].w));
            uint32_t r4 = h2u(__floats2half2_rn(rf[2].x, rf[2].y));
            uint32_t r5 = h2u(__floats2half2_rn(rf[2].z, rf[2].w));
            uint32_t r6 = h2u(__floats2half2_rn(rf[3].x, rf[3].y));
            uint32_t r7 = h2u(__floats2half2_rn(rf[3].z, rf[3].w));
            uint4* p = (uint4*)(As + arow * 80 + acol * 2);
            p[0] = make_uint4(r0, r1, r2, r3);
            p[1] = make_uint4(r4, r5, r6, r7);
        };
        auto cpA16 = [&](int stage, int gc) {
            uint32_t sA = smem_u32(Abase + stage * ASTAGE);
            const __half* A = (const __half*)Ain;
#pragma unroll
            for (int t = 0; t < 2; t++) {
                int idx = tid + t * 256;
                int row = idx >> 2, c16 = idx & 3;
                int gr = m0 + row;
                uint32_t ok = (gr < M) ? 16u : 0u;
                int grc = (gr < M) ? gr : 0;
                cp_async16(sA + row * 80 + c16 * 16, A + (size_t)grc * Kreal + gc * 32 + c16 * 8, ok);
            }
        };
        auto cpB = [&](int stage, int gc) {
            uint32_t sB = smem_u32(Bbase + stage * BSTAGE);
#pragma unroll
            for (int t = 0; t < 2; t++) {
                int idx = tid + t * 256;
                int row = idx >> 2, c16 = idx & 3;
                cp_async16(sB + row * 80 + c16 * 16, Bt + (size_t)(n0 + row) * KB + gc * 32 + c16 * 8, 16u);
            }
        };

        auto compute = [&](int stage) {
            char* As = Abase + stage * ASTAGE;
            char* Bs = Bbase + stage * BSTAGE;
            uint32_t sAu = smem_u32(As);
            uint32_t sBu = smem_u32(Bs);
#pragma unroll
            for (int ks = 0; ks < 32; ks += 16) {
                uint32_t af[2][4], bf[8][2];
#pragma unroll
                for (int mt = 0; mt < 2; mt++) {
                    int r = wm * 32 + mt * 16 + (grp & 1) * 8 + lr;
                    int kb = ks + (grp >> 1) * 8;
                    ldmx4(af[mt], sAu + r * 80 + kb * 2);
                }
#pragma unroll
                for (int np = 0; np < 4; np++) {
                    int r = wn * 64 + np * 16 + (grp >> 1) * 8 + lr;
                    int kb = ks + (grp & 1) * 8;
                    uint32_t t4[4];
                    ldmx4(t4, sBu + r * 80 + kb * 2);
                    bf[np * 2 + 0][0] = t4[0];
                    bf[np * 2 + 0][1] = t4[1];
                    bf[np * 2 + 1][0] = t4[2];
                    bf[np * 2 + 1][1] = t4[3];
                }
#pragma unroll
                for (int mt = 0; mt < 2; mt++)
#pragma unroll
                    for (int nt = 0; nt < 8; nt++)
                        mma16816(acc[mt][nt], af[mt], bf[nt]);
            }
        };

        for (int s = 0; s < NS - 1; s++) {
            if (s < NC) {
                if (AF32) { ldgA(kc0 + s); stsA(s); }
                else      cpA16(s, kc0 + s);
                cpB(s, kc0 + s);
            }
            CP_COMMIT();
        }

        for (int c = 0; c < NC; c++) {
            cp_wait<NS - 2>();
            __syncthreads();
            int cn = c + NS - 1;
            if (AF32 && cn < NC) ldgA(kc0 + cn);
            compute(c % NS);
            if (cn < NC) {
                if (AF32) stsA(cn % NS);
                else      cpA16(cn % NS, kc0 + cn);
                cpB(cn % NS, kc0 + cn);
            }
            CP_COMMIT();
        }

        // epilogue: fp16 (direct or split-K partial)
        __half* cdst = AF32 ? (Cp + (size_t)kh * MPAD * Ntot) : C;
#pragma unroll
        for (int mt = 0; mt < 2; mt++) {
            int r1 = m0 + wm * 32 + mt * 16 + g;
            int r2 = r1 + 8;
#pragma unroll
            for (int nt = 0; nt < 8; nt++) {
                int col = n0 + wn * 64 + nt * 8 + tg * 2;
                if (r1 < M)
                    *(uint32_t*)(cdst + (size_t)r1 * Ntot + col) = h2u(__floats2half2_rn(acc[mt][nt][0], acc[mt][nt][1]));
                if (r2 < M)
                    *(uint32_t*)(cdst + (size_t)r2 * Ntot + col) = h2u(__floats2half2_rn(acc[mt][nt][2], acc[mt][nt][3]));
            }
        }
    }
}

// ---------------- fused combine (partials -> h0 fp16) + pq projections ---------------
// 4 threads/node: each sums 32 features (fp32), writes its h0 slice, computes 16
// partial dots, butterfly-reduces across the 4 threads, lane (gid&3)==0.. writes pq.
__global__ void combine_pq_kernel(const float* __restrict__ W1) {
    __shared__ float w[DF][16];
    for (int i = threadIdx.x; i < DF * 16; i += 256) {
        int f = i >> 4, o = i & 15;
        float v;
        if (o < 8) { int k = o >> 1, h = o & 1; v = W1[(k * 256 + f) * 2 + h]; }
        else       { int o8 = o - 8; int k = o8 >> 1, h = o8 & 1; v = W1[(k * 256 + 128 + f) * 2 + h]; }
        w[f][o] = v;
    }
    __syncthreads();

    int gid = blockIdx.x * 256 + threadIdx.x;
    int n  = gid >> 2;
    int q4 = gid & 3;            // feature quarter 0..3 (32 features each)
    if (n >= NN) return;

    const uint32_t* c0 = (const uint32_t*)(d_h0p + (size_t)n * DF) + q4 * 16;
    const uint32_t* c1 = (const uint32_t*)(d_h0p + (size_t)MP1 * DF + (size_t)n * DF) + q4 * 16;
    uint32_t* ho = (uint32_t*)(d_h0 + (size_t)n * DF) + q4 * 16;

    float acc[16];
#pragma unroll
    for (int o = 0; o < 16; o++) acc[o] = 0.0f;

#pragma unroll
    for (int j = 0; j < 16; j++) {
        uint32_t ra = c0[j], rb = c1[j];
        float2 xa = __half22float2(*reinterpret_cast<__half2*>(&ra));
        float2 xb = __half22float2(*reinterpret_cast<__half2*>(&rb));
        float x0 = xa.x + xb.x;
        float x1 = xa.y + xb.y;
        ho[j] = h2u(__floats2half2_rn(x0, x1));
        int f = q4 * 32 + j * 2;
#pragma unroll
        for (int o = 0; o < 16; o++)
            acc[o] += x0 * w[f][o] + x1 * w[f + 1][o];
    }
    // reduce the 16 dots across the 4 consecutive lanes of this node
#pragma unroll
    for (int o = 0; o < 16; o++) {
        acc[o] += __shfl_xor_sync(0xffffffffu, acc[o], 1);
        acc[o] += __shfl_xor_sync(0xffffffffu, acc[o], 2);
    }
    // each of the 4 lanes writes a distinct quarter of the 16 outputs
    *(float4*)(d_pqf + (size_t)n * 16 + q4 * 4) =
        make_float4(acc[q4 * 4 + 0], acc[q4 * 4 + 1], acc[q4 * 4 + 2], acc[q4 * 4 + 3]);
}

// ---------------- weight prep ----------------
__global__ void prep_weights(const float* __restrict__ Wh, const float* __restrict__ g1W,
                             const float* __restrict__ g2W) {
    int i = blockIdx.x * blockDim.x + threadIdx.x;
    if (i < DF * KPAD1) {
        int n = i / KPAD1, k = i % KPAD1;
        d_WhT[i] = (k < INDIM) ? __float2half(Wh[k * DF + n]) : __half(0.f);
    }
    if (i < H1D * DF) {
        int n = i / DF, k = i % DF;
        d_g1T[i] = __float2half(g1W[k * H1D + n]);
    }
    if (i < H2D * H1D) {
        int n = i / H1D, k = i % H1D;
        d_g2T[i] = __float2half(g2W[k * H2D + n]);
    }
}

// ---------------- init ----------------
__global__ void initA_kernel() {
    int i = blockIdx.x * blockDim.x + threadIdx.x;
    if (i < KD * NN) d_deg[i] = 1.0f;
}
__global__ void initB_kernel() {
    int i = blockIdx.x * blockDim.x + threadIdx.x;
    if (i < NN) d_fill[i] = 0;
    if (i < 32 * KD * H2D) ((float*)d_maccP)[i] = 0.0f;
}

// ---------------- edge gate ----------------
__global__ void edge_gate_kernel(const int* __restrict__ src, const int* __restrict__ dst,
                                 const float* __restrict__ b1, const float* __restrict__ W2,
                                 const float* __restrict__ b2, float* __restrict__ G) {
    int e = blockIdx.x * blockDim.x + threadIdx.x;
    if (e >= NE) return;
    int s = src[e];
    int d = dst[e];
    float4 p0 = *(const float4*)(d_pqf + (size_t)s * 16);
    float4 p1 = *(const float4*)(d_pqf + (size_t)s * 16 + 4);
    float4 q0 = *(const float4*)(d_pqf + (size_t)d * 16 + 8);
    float4 q1 = *(const float4*)(d_pqf + (size_t)d * 16 + 12);
    float pv[8] = {p0.x, p0.y, p0.z, p0.w, p1.x, p1.y, p1.z, p1.w};
    float qv[8] = {q0.x, q0.y, q0.z, q0.w, q1.x, q1.y, q1.z, q1.w};
#pragma unroll
    for (int k = 0; k < KD; k++) {
        float h0v = fmaxf(pv[k * 2 + 0] + qv[k * 2 + 0] + b1[k * 2 + 0], 0.0f);
        float h1v = fmaxf(pv[k * 2 + 1] + qv[k * 2 + 1] + b1[k * 2 + 1], 0.0f);
        float logit = h0v * W2[k * 2 + 0] + h1v * W2[k * 2 + 1] + b2[k];
        float gk = 1.0f / (1.0f + expf(-logit));
        G[k * NE + e] = gk;
        atomicAdd(&d_deg[k * NN + d], gk);
    }
    atomicAdd(&d_fill[d], 1);
}

__global__ void dinv_kernel() {
    int i = blockIdx.x * blockDim.x + threadIdx.x;
    if (i < KD * NN) d_dinv[i] = rsqrtf(d_deg[i]);
}

// ---------------- scan -> rowptr ----------------
__global__ void scanA_kernel() {
    __shared__ int s[1024];
    int t = threadIdx.x;
    int i = blockIdx.x * 1024 + t;
    int x = (i < NN) ? d_fill[i] : 0;
    s[t] = x;
    __syncthreads();
    for (int off = 1; off < 1024; off <<= 1) {
        int v = (t >= off) ? s[t - off] : 0;
        __syncthreads();
        s[t] += v;
        __syncthreads();
    }
    if (i < NN) d_rowptr[i] = s[t] - x;
    if (t == 1023) d_bsum[blockIdx.x] = s[1023];
}
__global__ void scanB_kernel(int nblk) {
    if (threadIdx.x == 0 && blockIdx.x == 0) {
        int run = 0;
        for (int b = 0; b < nblk; b++) { int v = d_bsum[b]; d_bsum[b] = run; run += v; }
        d_rowptr[NN] = run;
    }
}
__global__ void scanC_kernel() {
    int i = blockIdx.x * blockDim.x + threadIdx.x;
    if (i < NN) {
        int r = d_rowptr[i] + d_bsum[i >> 10];
        d_rowptr[i] = r;
        d_fill[i] = r;
    }
}

// ---------------- scatter into CSR + per-k norms ----------------
__global__ void scatter_kernel(const int* __restrict__ src, const int* __restrict__ dst,
                               const float* __restrict__ G) {
    int e = blockIdx.x * blockDim.x + threadIdx.x;
    if (e >= NE) return;
    int d = dst[e];
    int s = src[e];
    int pos = atomicAdd(&d_fill[d], 1);
    d_ssrc[pos] = s;
#pragma unroll
    for (int k = 0; k < KD; k++)
        d_norm[k * NE + pos] = d_dinv[k * NN + s] * G[k * NE + e] * d_dinv[k * NN + d];
}

// ---------------- GCN layer-1 aggregation ----------------
__global__ void agg1_kernel(const float* __restrict__ g1_b) {
    int w = threadIdx.x >> 5, l = threadIdx.x & 31;
    int n = blockIdx.x * 8 + w;
    if (n >= NN) return;

    float acc[KD][8];
#pragma unroll
    for (int k = 0; k < KD; k++)
#pragma unroll
        for (int j = 0; j < 8; j++) acc[k][j] = 0.0f;

    int beg = d_rowptr[n], end = d_rowptr[n + 1];
    for (int i = beg; i < end; i++) {
        int s = d_ssrc[i];
        uint4 raw = *((const uint4*)(d_h1 + (size_t)s * H1D) + l);
        __half2* hh = (__half2*)&raw;
        float2 f0 = __half22float2(hh[0]), f1 = __half22float2(hh[1]);
        float2 f2 = __half22float2(hh[2]), f3 = __half22float2(hh[3]);
#pragma unroll
        for (int k = 0; k < KD; k++) {
            float wg = d_norm[k * NE + i];
            acc[k][0] = fmaf(wg, f0.x, acc[k][0]); acc[k][1] = fmaf(wg, f0.y, acc[k][1]);
            acc[k][2] = fmaf(wg, f1.x, acc[k][2]); acc[k][3] = fmaf(wg, f1.y, acc[k][3]);
            acc[k][4] = fmaf(wg, f2.x, acc[k][4]); acc[k][5] = fmaf(wg, f2.y, acc[k][5]);
            acc[k][6] = fmaf(wg, f3.x, acc[k][6]); acc[k][7] = fmaf(wg, f3.y, acc[k][7]);
        }
    }
    {
        uint4 raw = *((const uint4*)(d_h1 + (size_t)n * H1D) + l);
        __half2* hh = (__half2*)&raw;
        float2 f0 = __half22float2(hh[0]), f1 = __half22float2(hh[1]);
        float2 f2 = __half22float2(hh[2]), f3 = __half22float2(hh[3]);
#pragma unroll
        for (int k = 0; k < KD; k++) {
            float dv = d_dinv[k * NN + n];
            float wg = dv * dv;
            acc[k][0] = fmaf(wg, f0.x, acc[k][0]); acc[k][1] = fmaf(wg, f0.y, acc[k][1]);
            acc[k][2] = fmaf(wg, f1.x, acc[k][2]); acc[k][3] = fmaf(wg, f1.y, acc[k][3]);
            acc[k][4] = fmaf(wg, f2.x, acc[k][4]); acc[k][5] = fmaf(wg, f2.y, acc[k][5]);
            acc[k][6] = fmaf(wg, f3.x, acc[k][6]); acc[k][7] = fmaf(wg, f3.y, acc[k][7]);
        }
    }
    float4 b0 = ((const float4*)g1_b)[l * 2];
    float4 b1 = ((const float4*)g1_b)[l * 2 + 1];
#pragma unroll
    for (int k = 0; k < KD; k++) {
        uint32_t p0 = h2u(__floats2half2_rn(fmaxf(acc[k][0] + b0.x, 0.f), fmaxf(acc[k][1] + b0.y, 0.f)));
        uint32_t p1 = h2u(__floats2half2_rn(fmaxf(acc[k][2] + b0.z, 0.f), fmaxf(acc[k][3] + b0.w, 0.f)));
        uint32_t p2 = h2u(__floats2half2_rn(fmaxf(acc[k][4] + b1.x, 0.f), fmaxf(acc[k][5] + b1.y, 0.f)));
        uint32_t p3 = h2u(__floats2half2_rn(fmaxf(acc[k][6] + b1.z, 0.f), fmaxf(acc[k][7] + b1.w, 0.f)));
        *((uint4*)(d_z1 + ((size_t)(k * NN + n)) * H1D) + l) = make_uint4(p0, p1, p2, p3);
    }
}

// ---------------- GCN layer-2 aggregation + mean accum (striped partials) -------------
__global__ void agg2_kernel(const float* __restrict__ g2_b) {
    __shared__ float sacc[H2D];
    int t = threadIdx.x;
    int k = blockIdx.y;
    if (t < H2D) sacc[t] = 0.0f;
    __syncthreads();

    int w = t >> 5, l = t & 31;
    int n = blockIdx.x * 8 + w;
    if (n < NN) {
        float a0 = 0.f, a1 = 0.f, a2 = 0.f, a3 = 0.f;
        const __half* h2k = d_h2 + (size_t)k * NN * H2D;
        const float*  nrm = d_norm + (size_t)k * NE;

        int beg = d_rowptr[n], end = d_rowptr[n + 1];
        for (int i = beg; i < end; i++) {
            int s = d_ssrc[i];
            float wg = nrm[i];
            uint2 raw = *((const uint2*)(h2k + (size_t)s * H2D) + l);
            __half2* hh = (__half2*)&raw;
            float2 f0 = __half22float2(hh[0]), f1 = __half22float2(hh[1]);
            a0 = fmaf(wg, f0.x, a0); a1 = fmaf(wg, f0.y, a1);
            a2 = fmaf(wg, f1.x, a2); a3 = fmaf(wg, f1.y, a3);
        }
        {
            float dv = d_dinv[k * NN + n];
            float wg = dv * dv;
            uint2 raw = *((const uint2*)(h2k + (size_t)n * H2D) + l);
            __half2* hh = (__half2*)&raw;
            float2 f0 = __half22float2(hh[0]), f1 = __half22float2(hh[1]);
            a0 = fmaf(wg, f0.x, a0); a1 = fmaf(wg, f0.y, a1);
            a2 = fmaf(wg, f1.x, a2); a3 = fmaf(wg, f1.y, a3);
        }
        float4 b = ((const float4*)g2_b)[l];
        atomicAdd(&sacc[l * 4 + 0], fmaxf(a0 + b.x, 0.f));
        atomicAdd(&sacc[l * 4 + 1], fmaxf(a1 + b.y, 0.f));
        atomicAdd(&sacc[l * 4 + 2], fmaxf(a2 + b.z, 0.f));
        atomicAdd(&sacc[l * 4 + 3], fmaxf(a3 + b.w, 0.f));
    }
    __syncthreads();
    if (t < H2D) atomicAdd(&d_maccP[blockIdx.x & 31][k * H2D + t], sacc[t]);
}

// ---------------- reduce partials ----------------
__global__ void reduce_macc() {
    int i = threadIdx.x;
    float s = 0.0f;
#pragma unroll
    for (int p = 0; p < 32; p++) s += d_maccP[p][i];
    d_macc[i] = s;
}

// ---------------- final descriptors ----------------
__global__ void final_kernel(const float* __restrict__ fc_W, const float* __restrict__ fc_b,
                             float* __restrict__ out) {
    int t = threadIdx.x;
    int k = t >> 5, o = t & 31;
    const float inv = 1.0f / (float)NN;
    float s = fc_b[o];
    for (int d = 0; d < H2D; d++) s = fmaf(d_macc[k * H2D + d] * inv, fc_W[d * ODIM + o], s);
    out[t] = s;
}

// ---------------- launch ----------------
static void* symp(const void* s) {
    void* p = nullptr;
    cudaGetSymbolAddress(&p, s);
    return p;
}

extern "C" void kernel_launch(void* const* d_in, const int* in_sizes, int n_in,
                              void* d_out, int out_size) {
    const float* X     = (const float*)d_in[0];
    const int*   ei    = (const int*)d_in[1];
    const float* Wh    = (const float*)d_in[2];
    const float* W1    = (const float*)d_in[3];
    const float* b1    = (const float*)d_in[4];
    const float* W2    = (const float*)d_in[5];
    const float* b2    = (const float*)d_in[6];
    const float* g1_W  = (const float*)d_in[7];
    const float* g1_b  = (const float*)d_in[8];
    const float* g2_W  = (const float*)d_in[9];
    const float* g2_b  = (const float*)d_in[10];
    const float* fc_W  = (const float*)d_in[11];
    const float* fc_b  = (const float*)d_in[12];

    const int* src = ei;
    const int* dst = ei + NE;

    float* out = (float*)d_out;
    float* G   = out + KD * ODIM;

    __half* p_h0  = (__half*)symp(d_h0);
    __half* p_h1  = (__half*)symp(d_h1);
    __half* p_z1  = (__half*)symp(d_z1);
    __half* p_h2  = (__half*)symp(d_h2);
    __half* p_h0p = (__half*)symp(d_h0p);
    __half* p_WhT = (__half*)symp(d_WhT);
    __half* p_g1T = (__half*)symp(d_g1T);
    __half* p_g2T = (__half*)symp(d_g2T);

    const int SMEM = 4 * (128 * 80 + 128 * 80);   // 81920 -> 2 CTAs/SM
    cudaFuncSetAttribute((const void*)gemm_pipe<true, 4>,  cudaFuncAttributeMaxDynamicSharedMemorySize, SMEM);
    cudaFuncSetAttribute((const void*)gemm_pipe<false, 4>, cudaFuncAttributeMaxDynamicSharedMemorySize, SMEM);

    const int PGRID = 296;

    // launches #1-#3 so that gemm1 remains launch #4 (ncu samples #4)
    prep_weights<<<(DF * KPAD1 + 255) / 256, 256>>>(Wh, g1_W, g2_W);
    initA_kernel<<<(KD * NN + 255) / 256, 256>>>();
    initB_kernel<<<(NN + 255) / 256, 256>>>();

    // 1. (#4) h0 partials: split-K=2, fp16 partials (782 work units)
    gemm_pipe<true, 4><<<PGRID, 256, SMEM>>>(X, p_WhT, p_h0, p_h0p, NN, INDIM, KPAD1, DF,
                                             KPAD1 / 64, (NN + 127) / 128, 1, 2);

    // 1b. fused combine partials -> fp16 h0 + pq projections
    combine_pq_kernel<<<(NN * 4 + 255) / 256, 256>>>(W1);

    // 2. edge gates + degree accumulation + dst counts
    edge_gate_kernel<<<(NE + 255) / 256, 256>>>(src, dst, b1, W2, b2, G);

    // 3. dinv
    dinv_kernel<<<(KD * NN + 255) / 256, 256>>>();

    // 4. scan -> rowptr
    int nblk = (NN + 1023) / 1024;
    scanA_kernel<<<nblk, 1024>>>();
    scanB_kernel<<<1, 32>>>(nblk);
    scanC_kernel<<<(NN + 255) / 256, 256>>>();

    // 5. scatter CSR + norms
    scatter_kernel<<<(NE + 255) / 256, 256>>>(src, dst, G);

    // 6. h1 = fp16(h0 @ g1_W)
    gemm_pipe<false, 4><<<PGRID, 256, SMEM>>>(p_h0, p_g1T, p_h1, nullptr, NN, DF, DF, H1D,
                                              DF / 32, (NN + 127) / 128, 2, 1);

    // 7. layer-1 aggregation
    agg1_kernel<<<(NN + 7) / 8, 256>>>(g1_b);

    // 8. h2 = fp16(z1 @ g2_W)
    gemm_pipe<false, 4><<<PGRID, 256, SMEM>>>(p_z1, p_g2T, p_h2, nullptr, KD * NN, H1D, H1D, H2D,
                                              H1D / 32, (KD * NN + 127) / 128, 1, 1);

    // 9. layer-2 aggregation + mean accumulation
    {
        dim3 grid((NN + 7) / 8, KD);
        agg2_kernel<<<grid, 256>>>(g2_b);
    }

    // 9b. reduce partials
    reduce_macc<<<1, KD * H2D>>>();

    // 10. descriptors
    final_kernel<<<1, 128>>>(fc_W, fc_b, out);
}

// round 14
// speedup vs baseline: 1.0634x; 1.0634x over previous
#include <cuda_runtime.h>
#include <cuda_fp16.h>
#include <math.h>
#include <stdint.h>

#define NN    50000
#define NE    300000
#define INDIM 2000
#define DF    128
#define H1D   256
#define H2D   128
#define ODIM  32
#define KD    4
#define KPAD1 2048

// ---------------- scratch (static device globals; no allocation) ----------------
static __device__ __half d_h0[NN * DF];
static __device__ __half d_h1[NN * H1D];
static __device__ __half d_z1[KD * NN * H1D];
static __device__ __half d_h2[KD * NN * H2D];
static __device__ float  d_pqf[NN * 16];
static __device__ __half d_WhT[DF * KPAD1];
static __device__ __half d_g1T[H1D * DF];
static __device__ __half d_g2T[H2D * H1D];
static __device__ float d_deg[KD * NN];
static __device__ float d_dinv[KD * NN];
static __device__ float d_norm[KD * NE];
static __device__ int   d_rowptr[NN + 1];
static __device__ int   d_fill[NN];
static __device__ int   d_ssrc[NE];
static __device__ int   d_bsum[64];
static __device__ float d_maccP[32][KD * H2D];
static __device__ float d_macc[KD * H2D];

__device__ __forceinline__ uint32_t h2u(__half2 h) { return *reinterpret_cast<uint32_t*>(&h); }

__device__ __forceinline__ uint32_t smem_u32(const void* p) {
    uint32_t a;
    asm("{ .reg .u64 t; cvta.to.shared.u64 t, %1; cvt.u32.u64 %0, t; }" : "=r"(a) : "l"(p));
    return a;
}
__device__ __forceinline__ void cp_async16(uint32_t saddr, const void* gaddr, uint32_t ssize) {
    asm volatile("cp.async.cg.shared.global [%0], [%1], 16, %2;"
                 :: "r"(saddr), "l"(gaddr), "r"(ssize) : "memory");
}
#define CP_COMMIT() asm volatile("cp.async.commit_group;" ::: "memory")
template <int N>
__device__ __forceinline__ void cp_wait() {
    asm volatile("cp.async.wait_group %0;" :: "n"(N) : "memory");
}
__device__ __forceinline__ void ldmx4(uint32_t* r, uint32_t addr) {
    asm volatile("ldmatrix.sync.aligned.m8n8.x4.shared.b16 {%0,%1,%2,%3}, [%4];"
                 : "=r"(r[0]), "=r"(r[1]), "=r"(r[2]), "=r"(r[3]) : "r"(addr));
}
__device__ __forceinline__ void mma16816(float* d, const uint32_t* a, const uint32_t* b) {
    asm volatile("mma.sync.aligned.m16n8k16.row.col.f32.f16.f16.f32 "
                 "{%0,%1,%2,%3}, {%4,%5,%6,%7}, {%8,%9}, {%0,%1,%2,%3};"
                 : "+f"(d[0]), "+f"(d[1]), "+f"(d[2]), "+f"(d[3])
                 : "r"(a[0]), "r"(a[1]), "r"(a[2]), "r"(a[3]), "r"(b[0]), "r"(b[1]));
}

// ---------------- non-persistent cp.async HMMA GEMM, unified fp16 smem + ldmatrix -----
// Block tile 128x128, BK=32, 8 warps (4m x 2n), NS=4 stages (82KB, 2 CTAs/SM).
// AF32: A fp32 in gmem, converted at copy time (LDG -> cvt -> STS). Direct fp16 out.
template <bool AF32, int NS>
__global__ void __launch_bounds__(256, 2) gemm_pipe(const void* __restrict__ Ain,
                                                    const __half* __restrict__ Bt,
                                                    __half* __restrict__ C,
                                                    int M, int Kreal, int KB, int Ntot,
                                                    int NC) {
    extern __shared__ char sm[];
    const int ASTAGE = 128 * 80;
    const int BSTAGE = 128 * 80;
    char* Abase = sm;
    char* Bbase = sm + NS * ASTAGE;

    const int tid = threadIdx.x, lane = tid & 31, w = tid >> 5;
    const int wm = w & 3, wn = w >> 2;
    const int g = lane >> 2, tg = lane & 3;
    const int lr = lane & 7, grp = lane >> 3;
    const int m0 = blockIdx.x * 128;
    const int n0 = blockIdx.y * 128;

    const int arow = tid >> 1;
    const int acol = (tid & 1) * 16;

    float acc[2][8][4];
#pragma unroll
    for (int i = 0; i < 2; i++)
#pragma unroll
        for (int j = 0; j < 8; j++)
#pragma unroll
            for (int q = 0; q < 4; q++) acc[i][j][q] = 0.0f;

    float4 rf[4];

    auto ldgA = [&](int gc) {
        const float* A = (const float*)Ain;
        int gr = m0 + arow;
        bool rok = gr < M;
        int grc = rok ? gr : 0;
        const float* base = A + (size_t)grc * Kreal + gc * 32 + acol;
#pragma unroll
        for (int q = 0; q < 4; q++) {
            int col = gc * 32 + acol + q * 4;
            rf[q] = (rok && col < Kreal) ? *(const float4*)(base + q * 4)
                                         : make_float4(0.f, 0.f, 0.f, 0.f);
        }
    };
    auto stsA = [&](int stage) {
        char* As = Abase + stage * ASTAGE;
        uint32_t r0 = h2u(__floats2half2_rn(rf[0].x, rf[0].y));
        uint32_t r1 = h2u(__floats2half2_rn(rf[0].z, rf[0].w));
        uint32_t r2 = h2u(__floats2half2_rn(rf[1].x, rf[1].y));
        uint32_t r3 = h2u(__floats2half2_rn(rf[1].z, rf[1].w));
        uint32_t r4 = h2u(__floats2half2_rn(rf[2].x, rf[2].y));
        uint32_t r5 = h2u(__floats2half2_rn(rf[2].z, rf[2].w));
        uint32_t r6 = h2u(__floats2half2_rn(rf[3].x, rf[3].y));
        uint32_t r7 = h2u(__floats2half2_rn(rf[3].z, rf[3].w));
        uint4* p = (uint4*)(As + arow * 80 + acol * 2);
        p[0] = make_uint4(r0, r1, r2, r3);
        p[1] = make_uint4(r4, r5, r6, r7);
    };
    auto cpA16 = [&](int stage, int gc) {
        uint32_t sA = smem_u32(Abase + stage * ASTAGE);
        const __half* A = (const __half*)Ain;
#pragma unroll
        for (int t = 0; t < 2; t++) {
            int idx = tid + t * 256;
            int row = idx >> 2, c16 = idx & 3;
            int gr = m0 + row;
            uint32_t ok = (gr < M) ? 16u : 0u;
            int grc = (gr < M) ? gr : 0;
            cp_async16(sA + row * 80 + c16 * 16, A + (size_t)grc * Kreal + gc * 32 + c16 * 8, ok);
        }
    };
    auto cpB = [&](int stage, int gc) {
        uint32_t sB = smem_u32(Bbase + stage * BSTAGE);
#pragma unroll
        for (int t = 0; t < 2; t++) {
            int idx = tid + t * 256;
            int row = idx >> 2, c16 = idx & 3;
            cp_async16(sB + row * 80 + c16 * 16, Bt + (size_t)(n0 + row) * KB + gc * 32 + c16 * 8, 16u);
        }
    };

    auto compute = [&](int stage) {
        char* As = Abase + stage * ASTAGE;
        char* Bs = Bbase + stage * BSTAGE;
        uint32_t sAu = smem_u32(As);
        uint32_t sBu = smem_u32(Bs);
#pragma unroll
        for (int ks = 0; ks < 32; ks += 16) {
            uint32_t af[2][4], bf[8][2];
#pragma unroll
            for (int mt = 0; mt < 2; mt++) {
                int r = wm * 32 + mt * 16 + (grp & 1) * 8 + lr;
                int kb = ks + (grp >> 1) * 8;
                ldmx4(af[mt], sAu + r * 80 + kb * 2);
            }
#pragma unroll
            for (int np = 0; np < 4; np++) {
                int r = wn * 64 + np * 16 + (grp >> 1) * 8 + lr;
                int kb = ks + (grp & 1) * 8;
                uint32_t t4[4];
                ldmx4(t4, sBu + r * 80 + kb * 2);
                bf[np * 2 + 0][0] = t4[0];
                bf[np * 2 + 0][1] = t4[1];
                bf[np * 2 + 1][0] = t4[2];
                bf[np * 2 + 1][1] = t4[3];
            }
#pragma unroll
            for (int mt = 0; mt < 2; mt++)
#pragma unroll
                for (int nt = 0; nt < 8; nt++)
                    mma16816(acc[mt][nt], af[mt], bf[nt]);
        }
    };

    for (int s = 0; s < NS - 1; s++) {
        if (s < NC) {
            if (AF32) { ldgA(s); stsA(s); }
            else      cpA16(s, s);
            cpB(s, s);
        }
        CP_COMMIT();
    }

    for (int c = 0; c < NC; c++) {
        cp_wait<NS - 2>();
        __syncthreads();
        int cn = c + NS - 1;
        if (AF32 && cn < NC) ldgA(cn);   // LDG issued early, hidden under compute
        compute(c % NS);
        if (cn < NC) {
            if (AF32) stsA(cn % NS);
            else      cpA16(cn % NS, cn);
            cpB(cn % NS, cn);
        }
        CP_COMMIT();
    }

#pragma unroll
    for (int mt = 0; mt < 2; mt++) {
        int r1 = m0 + wm * 32 + mt * 16 + g;
        int r2 = r1 + 8;
#pragma unroll
        for (int nt = 0; nt < 8; nt++) {
            int col = n0 + wn * 64 + nt * 8 + tg * 2;
            if (r1 < M)
                *(uint32_t*)(C + (size_t)r1 * Ntot + col) = h2u(__floats2half2_rn(acc[mt][nt][0], acc[mt][nt][1]));
            if (r2 < M)
                *(uint32_t*)(C + (size_t)r2 * Ntot + col) = h2u(__floats2half2_rn(acc[mt][nt][2], acc[mt][nt][3]));
        }
    }
}

// ---------------- weight prep ----------------
__global__ void prep_weights(const float* __restrict__ Wh, const float* __restrict__ g1W,
                             const float* __restrict__ g2W) {
    int i = blockIdx.x * blockDim.x + threadIdx.x;
    if (i < DF * KPAD1) {
        int n = i / KPAD1, k = i % KPAD1;
        d_WhT[i] = (k < INDIM) ? __float2half(Wh[k * DF + n]) : __half(0.f);
    }
    if (i < H1D * DF) {
        int n = i / DF, k = i % DF;
        d_g1T[i] = __float2half(g1W[k * H1D + n]);
    }
    if (i < H2D * H1D) {
        int n = i / H1D, k = i % H1D;
        d_g2T[i] = __float2half(g2W[k * H2D + n]);
    }
}

// ---------------- init ----------------
__global__ void initA_kernel() {
    int i = blockIdx.x * blockDim.x + threadIdx.x;
    if (i < KD * NN) d_deg[i] = 1.0f;
}
__global__ void initB_kernel() {
    int i = blockIdx.x * blockDim.x + threadIdx.x;
    if (i < NN) d_fill[i] = 0;
    if (i < 32 * KD * H2D) ((float*)d_maccP)[i] = 0.0f;
}

// ---------------- per-node edge-MLP projections: 4 threads/node ----------------
__global__ void pq_kernel(const float* __restrict__ W1) {
    __shared__ float w[DF][16];
    for (int i = threadIdx.x; i < DF * 16; i += 256) {
        int f = i >> 4, o = i & 15;
        float v;
        if (o < 8) { int k = o >> 1, h = o & 1; v = W1[(k * 256 + f) * 2 + h]; }
        else       { int o8 = o - 8; int k = o8 >> 1, h = o8 & 1; v = W1[(k * 256 + 128 + f) * 2 + h]; }
        w[f][o] = v;
    }
    __syncthreads();

    int gid = blockIdx.x * 256 + threadIdx.x;
    int n  = gid >> 2;
    int og = (gid & 3) * 4;
    if (n >= NN) return;

    float a0 = 0.f, a1 = 0.f, a2 = 0.f, a3 = 0.f;
    const uint32_t* hu = (const uint32_t*)(d_h0 + (size_t)n * DF);
#pragma unroll
    for (int j = 0; j < 64; j++) {
        uint32_t raw = hu[j];
        __half2 hx = *reinterpret_cast<__half2*>(&raw);
        float2 x = __half22float2(hx);
        int f = j * 2;
        a0 += x.x * w[f][og + 0] + x.y * w[f + 1][og + 0];
        a1 += x.x * w[f][og + 1] + x.y * w[f + 1][og + 1];
        a2 += x.x * w[f][og + 2] + x.y * w[f + 1][og + 2];
        a3 += x.x * w[f][og + 3] + x.y * w[f + 1][og + 3];
    }
    *(float4*)(d_pqf + (size_t)n * 16 + og) = make_float4(a0, a1, a2, a3);
}

// ---------------- edge gate ----------------
__global__ void edge_gate_kernel(const int* __restrict__ src, const int* __restrict__ dst,
                                 const float* __restrict__ b1, const float* __restrict__ W2,
                                 const float* __restrict__ b2, float* __restrict__ G) {
    int e = blockIdx.x * blockDim.x + threadIdx.x;
    if (e >= NE) return;
    int s = src[e];
    int d = dst[e];
    float4 p0 = *(const float4*)(d_pqf + (size_t)s * 16);
    float4 p1 = *(const float4*)(d_pqf + (size_t)s * 16 + 4);
    float4 q0 = *(const float4*)(d_pqf + (size_t)d * 16 + 8);
    float4 q1 = *(const float4*)(d_pqf + (size_t)d * 16 + 12);
    float pv[8] = {p0.x, p0.y, p0.z, p0.w, p1.x, p1.y, p1.z, p1.w};
    float qv[8] = {q0.x, q0.y, q0.z, q0.w, q1.x, q1.y, q1.z, q1.w};
#pragma unroll
    for (int k = 0; k < KD; k++) {
        float h0v = fmaxf(pv[k * 2 + 0] + qv[k * 2 + 0] + b1[k * 2 + 0], 0.0f);
        float h1v = fmaxf(pv[k * 2 + 1] + qv[k * 2 + 1] + b1[k * 2 + 1], 0.0f);
        float logit = h0v * W2[k * 2 + 0] + h1v * W2[k * 2 + 1] + b2[k];
        float gk = 1.0f / (1.0f + expf(-logit));
        G[k * NE + e] = gk;
        atomicAdd(&d_deg[k * NN + d], gk);
    }
    atomicAdd(&d_fill[d], 1);
}

__global__ void dinv_kernel() {
    int i = blockIdx.x * blockDim.x + threadIdx.x;
    if (i < KD * NN) d_dinv[i] = rsqrtf(d_deg[i]);
}

// ---------------- scan -> rowptr ----------------
__global__ void scanA_kernel() {
    __shared__ int s[1024];
    int t = threadIdx.x;
    int i = blockIdx.x * 1024 + t;
    int x = (i < NN) ? d_fill[i] : 0;
    s[t] = x;
    __syncthreads();
    for (int off = 1; off < 1024; off <<= 1) {
        int v = (t >= off) ? s[t - off] : 0;
        __syncthreads();
        s[t] += v;
        __syncthreads();
    }
    if (i < NN) d_rowptr[i] = s[t] - x;
    if (t == 1023) d_bsum[blockIdx.x] = s[1023];
}
__global__ void scanB_kernel(int nblk) {
    if (threadIdx.x == 0 && blockIdx.x == 0) {
        int run = 0;
        for (int b = 0; b < nblk; b++) { int v = d_bsum[b]; d_bsum[b] = run; run += v; }
        d_rowptr[NN] = run;
    }
}
__global__ void scanC_kernel() {
    int i = blockIdx.x * blockDim.x + threadIdx.x;
    if (i < NN) {
        int r = d_rowptr[i] + d_bsum[i >> 10];
        d_rowptr[i] = r;
        d_fill[i] = r;
    }
}

// ---------------- scatter into CSR + per-k norms ----------------
__global__ void scatter_kernel(const int* __restrict__ src, const int* __restrict__ dst,
                               const float* __restrict__ G) {
    int e = blockIdx.x * blockDim.x + threadIdx.x;
    if (e >= NE) return;
    int d = dst[e];
    int s = src[e];
    int pos = atomicAdd(&d_fill[d], 1);
    d_ssrc[pos] = s;
#pragma unroll
    for (int k = 0; k < KD; k++)
        d_norm[k * NE + pos] = d_dinv[k * NN + s] * G[k * NE + e] * d_dinv[k * NN + d];
}

// ---------------- GCN layer-1 aggregation ----------------
__global__ void agg1_kernel(const float* __restrict__ g1_b) {
    int w = threadIdx.x >> 5, l = threadIdx.x & 31;
    int n = blockIdx.x * 8 + w;
    if (n >= NN) return;

    float acc[KD][8];
#pragma unroll
    for (int k = 0; k < KD; k++)
#pragma unroll
        for (int j = 0; j < 8; j++) acc[k][j] = 0.0f;

    int beg = d_rowptr[n], end = d_rowptr[n + 1];
    for (int i = beg; i < end; i++) {
        int s = d_ssrc[i];
        uint4 raw = *((const uint4*)(d_h1 + (size_t)s * H1D) + l);
        __half2* hh = (__half2*)&raw;
        float2 f0 = __half22float2(hh[0]), f1 = __half22float2(hh[1]);
        float2 f2 = __half22float2(hh[2]), f3 = __half22float2(hh[3]);
#pragma unroll
        for (int k = 0; k < KD; k++) {
            float wg = d_norm[k * NE + i];
            acc[k][0] = fmaf(wg, f0.x, acc[k][0]); acc[k][1] = fmaf(wg, f0.y, acc[k][1]);
            acc[k][2] = fmaf(wg, f1.x, acc[k][2]); acc[k][3] = fmaf(wg, f1.y, acc[k][3]);
            acc[k][4] = fmaf(wg, f2.x, acc[k][4]); acc[k][5] = fmaf(wg, f2.y, acc[k][5]);
            acc[k][6] = fmaf(wg, f3.x, acc[k][6]); acc[k][7] = fmaf(wg, f3.y, acc[k][7]);
        }
    }
    {
        uint4 raw = *((const uint4*)(d_h1 + (size_t)n * H1D) + l);
        __half2* hh = (__half2*)&raw;
        float2 f0 = __half22float2(hh[0]), f1 = __half22float2(hh[1]);
        float2 f2 = __half22float2(hh[2]), f3 = __half22float2(hh[3]);
#pragma unroll
        for (int k = 0; k < KD; k++) {
            float dv = d_dinv[k * NN + n];
            float wg = dv * dv;
            acc[k][0] = fmaf(wg, f0.x, acc[k][0]); acc[k][1] = fmaf(wg, f0.y, acc[k][1]);
            acc[k][2] = fmaf(wg, f1.x, acc[k][2]); acc[k][3] = fmaf(wg, f1.y, acc[k][3]);
            acc[k][4] = fmaf(wg, f2.x, acc[k][4]); acc[k][5] = fmaf(wg, f2.y, acc[k][5]);
            acc[k][6] = fmaf(wg, f3.x, acc[k][6]); acc[k][7] = fmaf(wg, f3.y, acc[k][7]);
        }
    }
    float4 b0 = ((const float4*)g1_b)[l * 2];
    float4 b1 = ((const float4*)g1_b)[l * 2 + 1];
#pragma unroll
    for (int k = 0; k < KD; k++) {
        uint32_t p0 = h2u(__floats2half2_rn(fmaxf(acc[k][0] + b0.x, 0.f), fmaxf(acc[k][1] + b0.y, 0.f)));
        uint32_t p1 = h2u(__floats2half2_rn(fmaxf(acc[k][2] + b0.z, 0.f), fmaxf(acc[k][3] + b0.w, 0.f)));
        uint32_t p2 = h2u(__floats2half2_rn(fmaxf(acc[k][4] + b1.x, 0.f), fmaxf(acc[k][5] + b1.y, 0.f)));
        uint32_t p3 = h2u(__floats2half2_rn(fmaxf(acc[k][6] + b1.z, 0.f), fmaxf(acc[k][7] + b1.w, 0.f)));
        *((uint4*)(d_z1 + ((size_t)(k * NN + n)) * H1D) + l) = make_uint4(p0, p1, p2, p3);
    }
}

// ---------------- GCN layer-2 aggregation + mean accum (striped partials) -------------
__global__ void agg2_kernel(const float* __restrict__ g2_b) {
    __shared__ float sacc[H2D];
    int t = threadIdx.x;
    int k = blockIdx.y;
    if (t < H2D) sacc[t] = 0.0f;
    __syncthreads();

    int w = t >> 5, l = t & 31;
    int n = blockIdx.x * 8 + w;
    if (n < NN) {
        float a0 = 0.f, a1 = 0.f, a2 = 0.f, a3 = 0.f;
        const __half* h2k = d_h2 + (size_t)k * NN * H2D;
        const float*  nrm = d_norm + (size_t)k * NE;

        int beg = d_rowptr[n], end = d_rowptr[n + 1];
        for (int i = beg; i < end; i++) {
            int s = d_ssrc[i];
            float wg = nrm[i];
            uint2 raw = *((const uint2*)(h2k + (size_t)s * H2D) + l);
            __half2* hh = (__half2*)&raw;
            float2 f0 = __half22float2(hh[0]), f1 = __half22float2(hh[1]);
            a0 = fmaf(wg, f0.x, a0); a1 = fmaf(wg, f0.y, a1);
            a2 = fmaf(wg, f1.x, a2); a3 = fmaf(wg, f1.y, a3);
        }
        {
            float dv = d_dinv[k * NN + n];
            float wg = dv * dv;
            uint2 raw = *((const uint2*)(h2k + (size_t)n * H2D) + l);
            __half2* hh = (__half2*)&raw;
            float2 f0 = __half22float2(hh[0]), f1 = __half22float2(hh[1]);
            a0 = fmaf(wg, f0.x, a0); a1 = fmaf(wg, f0.y, a1);
            a2 = fmaf(wg, f1.x, a2); a3 = fmaf(wg, f1.y, a3);
        }
        float4 b = ((const float4*)g2_b)[l];
        atomicAdd(&sacc[l * 4 + 0], fmaxf(a0 + b.x, 0.f));
        atomicAdd(&sacc[l * 4 + 1], fmaxf(a1 + b.y, 0.f));
        atomicAdd(&sacc[l * 4 + 2], fmaxf(a2 + b.z, 0.f));
        atomicAdd(&sacc[l * 4 + 3], fmaxf(a3 + b.w, 0.f));
    }
    __syncthreads();
    if (t < H2D) atomicAdd(&d_maccP[blockIdx.x & 31][k * H2D + t], sacc[t]);
}

// ---------------- reduce partials ----------------
__global__ void reduce_macc() {
    int i = threadIdx.x;
    float s = 0.0f;
#pragma unroll
    for (int p = 0; p < 32; p++) s += d_maccP[p][i];
    d_macc[i] = s;
}

// ---------------- final descriptors ----------------
__global__ void final_kernel(const float* __restrict__ fc_W, const float* __restrict__ fc_b,
                             float* __restrict__ out) {
    int t = threadIdx.x;
    int k = t >> 5, o = t & 31;
    const float inv = 1.0f / (float)NN;
    float s = fc_b[o];
    for (int d = 0; d < H2D; d++) s = fmaf(d_macc[k * H2D + d] * inv, fc_W[d * ODIM + o], s);
    out[t] = s;
}

// ---------------- launch ----------------
static void* symp(const void* s) {
    void* p = nullptr;
    cudaGetSymbolAddress(&p, s);
    return p;
}

extern "C" void kernel_launch(void* const* d_in, const int* in_sizes, int n_in,
                              void* d_out, int out_size) {
    const float* X     = (const float*)d_in[0];
    const int*   ei    = (const int*)d_in[1];
    const float* Wh    = (const float*)d_in[2];
    const float* W1    = (const float*)d_in[3];
    const float* b1    = (const float*)d_in[4];
    const float* W2    = (const float*)d_in[5];
    const float* b2    = (const float*)d_in[6];
    const float* g1_W  = (const float*)d_in[7];
    const float* g1_b  = (const float*)d_in[8];
    const float* g2_W  = (const float*)d_in[9];
    const float* g2_b  = (const float*)d_in[10];
    const float* fc_W  = (const float*)d_in[11];
    const float* fc_b  = (const float*)d_in[12];

    const int* src = ei;
    const int* dst = ei + NE;

    float* out = (float*)d_out;
    float* G   = out + KD * ODIM;

    __half* p_h0  = (__half*)symp(d_h0);
    __half* p_h1  = (__half*)symp(d_h1);
    __half* p_z1  = (__half*)symp(d_z1);
    __half* p_h2  = (__half*)symp(d_h2);
    __half* p_WhT = (__half*)symp(d_WhT);
    __half* p_g1T = (__half*)symp(d_g1T);
    __half* p_g2T = (__half*)symp(d_g2T);

    const int SMEM = 4 * (128 * 80 + 128 * 80);   // 81920 -> 2 CTAs/SM
    cudaFuncSetAttribute((const void*)gemm_pipe<true, 4>,  cudaFuncAttributeMaxDynamicSharedMemorySize, SMEM);
    cudaFuncSetAttribute((const void*)gemm_pipe<false, 4>, cudaFuncAttributeMaxDynamicSharedMemorySize, SMEM);

    // launches #1-#3 so that gemm1 remains launch #4 (ncu samples #4)
    prep_weights<<<(DF * KPAD1 + 255) / 256, 256>>>(Wh, g1_W, g2_W);
    initA_kernel<<<(KD * NN + 255) / 256, 256>>>();
    initB_kernel<<<(NN + 255) / 256, 256>>>();

    // 1. (#4) h0 = fp16(X @ Wh) — non-persistent, A converted at copy, direct fp16 out
    {
        dim3 grid((NN + 127) / 128, 1);
        gemm_pipe<true, 4><<<grid, 256, SMEM>>>(X, p_WhT, p_h0, NN, INDIM, KPAD1, DF, KPAD1 / 32);
    }

    // 1b. per-node edge-MLP projections
    pq_kernel<<<(NN * 4 + 255) / 256, 256>>>(W1);

    // 2. edge gates + degree accumulation + dst counts
    edge_gate_kernel<<<(NE + 255) / 256, 256>>>(src, dst, b1, W2, b2, G);

    // 3. dinv
    dinv_kernel<<<(KD * NN + 255) / 256, 256>>>();

    // 4. scan -> rowptr
    int nblk = (NN + 1023) / 1024;
    scanA_kernel<<<nblk, 1024>>>();
    scanB_kernel<<<1, 32>>>(nblk);
    scanC_kernel<<<(NN + 255) / 256, 256>>>();

    // 5. scatter CSR + norms
    scatter_kernel<<<(NE + 255) / 256, 256>>>(src, dst, G);

    // 6. h1 = fp16(h0 @ g1_W) — non-persistent
    {
        dim3 grid((NN + 127) / 128, H1D / 128);
        gemm_pipe<false, 4><<<grid, 256, SMEM>>>(p_h0, p_g1T, p_h1, NN, DF, DF, H1D, DF / 32);
    }

    // 7. layer-1 aggregation
    agg1_kernel<<<(NN + 7) / 8, 256>>>(g1_b);

    // 8. h2 = fp16(z1 @ g2_W) — non-persistent
    {
        dim3 grid((KD * NN + 127) / 128, H2D / 128);
        gemm_pipe<false, 4><<<grid, 256, SMEM>>>(p_z1, p_g2T, p_h2, KD * NN, H1D, H1D, H2D, H1D / 32);
    }

    // 9. layer-2 aggregation + mean accumulation
    {
        dim3 grid((NN + 7) / 8, KD);
        agg2_kernel<<<grid, 256>>>(g2_b);
    }

    // 9b. reduce partials
    reduce_macc<<<1, KD * H2D>>>();

    // 10. descriptors
    final_kernel<<<1, 128>>>(fc_W, fc_b, out);
}

// round 15
// speedup vs baseline: 1.1195x; 1.0527x over previous
#include <cuda_runtime.h>
#include <cuda_fp16.h>
#include <math.h>
#include <stdint.h>

#define NN    50000
#define NE    300000
#define INDIM 2000
#define DF    128
#define H1D   256
#define H2D   128
#define ODIM  32
#define KD    4
#define KPAD1 2048

// ---------------- scratch (static device globals; no allocation) ----------------
static __device__ __half d_h0[NN * DF];
static __device__ __half d_h1[NN * H1D];
static __device__ __half d_z1[KD * NN * H1D];
static __device__ __half d_h2[KD * NN * H2D];
static __device__ float  d_pqf[NN * 16];
static __device__ __half d_WhT[DF * KPAD1];
static __device__ __half d_g1T[H1D * DF];
static __device__ __half d_g2T[H2D * H1D];
static __device__ float d_deg[KD * NN];
static __device__ float d_dinv[KD * NN];
static __device__ float d_norm4[NE * 4];          // interleaved [edge][k]
static __device__ int   d_rowptr[NN + 1];
static __device__ int   d_fill[NN];
static __device__ int   d_ssrc[NE];
static __device__ int   d_bsum[64];
static __device__ float d_maccP[32][KD * H2D];
static __device__ float d_macc[KD * H2D];

__device__ __forceinline__ uint32_t h2u(__half2 h) { return *reinterpret_cast<uint32_t*>(&h); }

__device__ __forceinline__ uint32_t smem_u32(const void* p) {
    uint32_t a;
    asm("{ .reg .u64 t; cvta.to.shared.u64 t, %1; cvt.u32.u64 %0, t; }" : "=r"(a) : "l"(p));
    return a;
}
__device__ __forceinline__ void cp_async16(uint32_t saddr, const void* gaddr, uint32_t ssize) {
    asm volatile("cp.async.cg.shared.global [%0], [%1], 16, %2;"
                 :: "r"(saddr), "l"(gaddr), "r"(ssize) : "memory");
}
#define CP_COMMIT() asm volatile("cp.async.commit_group;" ::: "memory")
template <int N>
__device__ __forceinline__ void cp_wait() {
    asm volatile("cp.async.wait_group %0;" :: "n"(N) : "memory");
}
__device__ __forceinline__ void ldmx4(uint32_t* r, uint32_t addr) {
    asm volatile("ldmatrix.sync.aligned.m8n8.x4.shared.b16 {%0,%1,%2,%3}, [%4];"
                 : "=r"(r[0]), "=r"(r[1]), "=r"(r[2]), "=r"(r[3]) : "r"(addr));
}
__device__ __forceinline__ void mma16816(float* d, const uint32_t* a, const uint32_t* b) {
    asm volatile("mma.sync.aligned.m16n8k16.row.col.f32.f16.f16.f32 "
                 "{%0,%1,%2,%3}, {%4,%5,%6,%7}, {%8,%9}, {%0,%1,%2,%3};"
                 : "+f"(d[0]), "+f"(d[1]), "+f"(d[2]), "+f"(d[3])
                 : "r"(a[0]), "r"(a[1]), "r"(a[2]), "r"(a[3]), "r"(b[0]), "r"(b[1]));
}

// ---------------- persistent cp.async HMMA GEMM (R11 config, best wall) ---------------
// Block tile 128x128, BK=32, 8 warps (4m x 2n). ldmatrix fragment loads (fp16 A + B);
// AF32 path: fp32 A smem (144B stride), scalar fragment loads + convert. Persistent.
template <bool AF32, int NS>
__global__ void __launch_bounds__(256, 2) gemm_pipe(const void* __restrict__ Ain,
                                                    const __half* __restrict__ Bt,
                                                    __half* __restrict__ C,
                                                    int M, int Kreal, int KB, int Ntot,
                                                    int NC, int ntm, int ntn) {
    extern __shared__ char sm[];
    const int ASTAGE = AF32 ? (128 * 144) : (128 * 80);
    const int BSTAGE = 128 * 80;
    char* Abase = sm;
    char* Bbase = sm + NS * ASTAGE;

    const int tid = threadIdx.x, lane = tid & 31, w = tid >> 5;
    const int wm = w & 3, wn = w >> 2;
    const int g = lane >> 2, tg = lane & 3;
    const int lr = lane & 7, grp = lane >> 3;
    const int ntiles = ntm * ntn;

    for (int tile = blockIdx.x; tile < ntiles; tile += gridDim.x) {
        const int m0 = (tile % ntm) * 128;
        const int n0 = (tile / ntm) * 128;

        __syncthreads();

        float acc[2][8][4];
#pragma unroll
        for (int i = 0; i < 2; i++)
#pragma unroll
            for (int j = 0; j < 8; j++)
#pragma unroll
                for (int q = 0; q < 4; q++) acc[i][j][q] = 0.0f;

        auto issue_copy = [&](int stage, int c) {
            uint32_t sA = smem_u32(Abase + stage * ASTAGE);
            uint32_t sB = smem_u32(Bbase + stage * BSTAGE);
            if (AF32) {
                const float* A = (const float*)Ain;
#pragma unroll
                for (int t = 0; t < 4; t++) {
                    int idx = tid + t * 256;
                    int row = idx >> 3, c16 = idx & 7;
                    int gr = m0 + row;
                    int gcol = c * 32 + c16 * 4;
                    uint32_t ok = (gr < M && gcol < Kreal) ? 16u : 0u;
                    int grc = (gr < M) ? gr : 0;
                    int gcc = (gcol < Kreal) ? gcol : 0;
                    cp_async16(sA + row * 144 + c16 * 16, A + (size_t)grc * Kreal + gcc, ok);
                }
            } else {
                const __half* A = (const __half*)Ain;
#pragma unroll
                for (int t = 0; t < 2; t++) {
                    int idx = tid + t * 256;
                    int row = idx >> 2, c16 = idx & 3;
                    int gr = m0 + row;
                    uint32_t ok = (gr < M) ? 16u : 0u;
                    int grc = (gr < M) ? gr : 0;
                    cp_async16(sA + row * 80 + c16 * 16, A + (size_t)grc * Kreal + c * 32 + c16 * 8, ok);
                }
            }
#pragma unroll
            for (int t = 0; t < 2; t++) {
                int idx = tid + t * 256;
                int row = idx >> 2, c16 = idx & 3;
                cp_async16(sB + row * 80 + c16 * 16, Bt + (size_t)(n0 + row) * KB + c * 32 + c16 * 8, 16u);
            }
        };

        auto compute = [&](int stage) {
            char* As = Abase + stage * ASTAGE;
            char* Bs = Bbase + stage * BSTAGE;
            uint32_t sAu = smem_u32(As);
            uint32_t sBu = smem_u32(Bs);
#pragma unroll
            for (int ks = 0; ks < 32; ks += 16) {
                uint32_t af[2][4], bf[8][2];
#pragma unroll
                for (int mt = 0; mt < 2; mt++) {
                    if (AF32) {
                        int r0 = wm * 32 + mt * 16 + g;
                        const float2* pA0 = (const float2*)(As + r0 * 144 + (ks + 2 * tg) * 4);
                        const float2* pA1 = (const float2*)(As + (r0 + 8) * 144 + (ks + 2 * tg) * 4);
                        float2 v0 = pA0[0], v1 = pA1[0], v2 = pA0[4], v3 = pA1[4];
                        af[mt][0] = h2u(__floats2half2_rn(v0.x, v0.y));
                        af[mt][1] = h2u(__floats2half2_rn(v1.x, v1.y));
                        af[mt][2] = h2u(__floats2half2_rn(v2.x, v2.y));
                        af[mt][3] = h2u(__floats2half2_rn(v3.x, v3.y));
                    } else {
                        int r = wm * 32 + mt * 16 + (grp & 1) * 8 + lr;
                        int kb = ks + (grp >> 1) * 8;
                        ldmx4(af[mt], sAu + r * 80 + kb * 2);
                    }
                }
#pragma unroll
                for (int np = 0; np < 4; np++) {
                    int r = wn * 64 + np * 16 + (grp >> 1) * 8 + lr;
                    int kb = ks + (grp & 1) * 8;
                    uint32_t t4[4];
                    ldmx4(t4, sBu + r * 80 + kb * 2);
                    bf[np * 2 + 0][0] = t4[0];
                    bf[np * 2 + 0][1] = t4[1];
                    bf[np * 2 + 1][0] = t4[2];
                    bf[np * 2 + 1][1] = t4[3];
                }
#pragma unroll
                for (int mt = 0; mt < 2; mt++)
#pragma unroll
                    for (int nt = 0; nt < 8; nt++)
                        mma16816(acc[mt][nt], af[mt], bf[nt]);
            }
        };

        for (int s = 0; s < NS - 1; s++) {
            if (s < NC) issue_copy(s, s);
            CP_COMMIT();
        }

        for (int c = 0; c < NC; c++) {
            cp_wait<NS - 2>();
            __syncthreads();
            compute(c % NS);
            int cn = c + NS - 1;
            if (cn < NC) issue_copy(cn % NS, cn);
            CP_COMMIT();
        }

#pragma unroll
        for (int mt = 0; mt < 2; mt++) {
            int r1 = m0 + wm * 32 + mt * 16 + g;
            int r2 = r1 + 8;
#pragma unroll
            for (int nt = 0; nt < 8; nt++) {
                int col = n0 + wn * 64 + nt * 8 + tg * 2;
                if (r1 < M)
                    *(uint32_t*)(C + (size_t)r1 * Ntot + col) = h2u(__floats2half2_rn(acc[mt][nt][0], acc[mt][nt][1]));
                if (r2 < M)
                    *(uint32_t*)(C + (size_t)r2 * Ntot + col) = h2u(__floats2half2_rn(acc[mt][nt][2], acc[mt][nt][3]));
            }
        }
    }
}

// ---------------- weight prep ----------------
__global__ void prep_weights(const float* __restrict__ Wh, const float* __restrict__ g1W,
                             const float* __restrict__ g2W) {
    int i = blockIdx.x * blockDim.x + threadIdx.x;
    if (i < DF * KPAD1) {
        int n = i / KPAD1, k = i % KPAD1;
        d_WhT[i] = (k < INDIM) ? __float2half(Wh[k * DF + n]) : __half(0.f);
    }
    if (i < H1D * DF) {
        int n = i / DF, k = i % DF;
        d_g1T[i] = __float2half(g1W[k * H1D + n]);
    }
    if (i < H2D * H1D) {
        int n = i / H1D, k = i % H1D;
        d_g2T[i] = __float2half(g2W[k * H2D + n]);
    }
}

// ---------------- init ----------------
__global__ void initA_kernel() {
    int i = blockIdx.x * blockDim.x + threadIdx.x;
    if (i < KD * NN) d_deg[i] = 1.0f;
}
__global__ void initB_kernel() {
    int i = blockIdx.x * blockDim.x + threadIdx.x;
    if (i < NN) d_fill[i] = 0;
    if (i < 32 * KD * H2D) ((float*)d_maccP)[i] = 0.0f;
}

// ---------------- per-node edge-MLP projections: 4 threads/node ----------------
__global__ void pq_kernel(const float* __restrict__ W1) {
    __shared__ float w[DF][16];
    for (int i = threadIdx.x; i < DF * 16; i += 256) {
        int f = i >> 4, o = i & 15;
        float v;
        if (o < 8) { int k = o >> 1, h = o & 1; v = W1[(k * 256 + f) * 2 + h]; }
        else       { int o8 = o - 8; int k = o8 >> 1, h = o8 & 1; v = W1[(k * 256 + 128 + f) * 2 + h]; }
        w[f][o] = v;
    }
    __syncthreads();

    int gid = blockIdx.x * 256 + threadIdx.x;
    int n  = gid >> 2;
    int og = (gid & 3) * 4;
    if (n >= NN) return;

    float a0 = 0.f, a1 = 0.f, a2 = 0.f, a3 = 0.f;
    const uint32_t* hu = (const uint32_t*)(d_h0 + (size_t)n * DF);
#pragma unroll
    for (int j = 0; j < 64; j++) {
        uint32_t raw = hu[j];
        __half2 hx = *reinterpret_cast<__half2*>(&raw);
        float2 x = __half22float2(hx);
        int f = j * 2;
        a0 += x.x * w[f][og + 0] + x.y * w[f + 1][og + 0];
        a1 += x.x * w[f][og + 1] + x.y * w[f + 1][og + 1];
        a2 += x.x * w[f][og + 2] + x.y * w[f + 1][og + 2];
        a3 += x.x * w[f][og + 3] + x.y * w[f + 1][og + 3];
    }
    *(float4*)(d_pqf + (size_t)n * 16 + og) = make_float4(a0, a1, a2, a3);
}

// ---------------- edge gate ----------------
__global__ void edge_gate_kernel(const int* __restrict__ src, const int* __restrict__ dst,
                                 const float* __restrict__ b1, const float* __restrict__ W2,
                                 const float* __restrict__ b2, float* __restrict__ G) {
    int e = blockIdx.x * blockDim.x + threadIdx.x;
    if (e >= NE) return;
    int s = src[e];
    int d = dst[e];
    float4 p0 = *(const float4*)(d_pqf + (size_t)s * 16);
    float4 p1 = *(const float4*)(d_pqf + (size_t)s * 16 + 4);
    float4 q0 = *(const float4*)(d_pqf + (size_t)d * 16 + 8);
    float4 q1 = *(const float4*)(d_pqf + (size_t)d * 16 + 12);
    float pv[8] = {p0.x, p0.y, p0.z, p0.w, p1.x, p1.y, p1.z, p1.w};
    float qv[8] = {q0.x, q0.y, q0.z, q0.w, q1.x, q1.y, q1.z, q1.w};
#pragma unroll
    for (int k = 0; k < KD; k++) {
        float h0v = fmaxf(pv[k * 2 + 0] + qv[k * 2 + 0] + b1[k * 2 + 0], 0.0f);
        float h1v = fmaxf(pv[k * 2 + 1] + qv[k * 2 + 1] + b1[k * 2 + 1], 0.0f);
        float logit = h0v * W2[k * 2 + 0] + h1v * W2[k * 2 + 1] + b2[k];
        float gk = 1.0f / (1.0f + expf(-logit));
        G[k * NE + e] = gk;
        atomicAdd(&d_deg[k * NN + d], gk);
    }
    atomicAdd(&d_fill[d], 1);
}

__global__ void dinv_kernel() {
    int i = blockIdx.x * blockDim.x + threadIdx.x;
    if (i < KD * NN) d_dinv[i] = rsqrtf(d_deg[i]);
}

// ---------------- scan -> rowptr ----------------
__global__ void scanA_kernel() {
    __shared__ int s[1024];
    int t = threadIdx.x;
    int i = blockIdx.x * 1024 + t;
    int x = (i < NN) ? d_fill[i] : 0;
    s[t] = x;
    __syncthreads();
    for (int off = 1; off < 1024; off <<= 1) {
        int v = (t >= off) ? s[t - off] : 0;
        __syncthreads();
        s[t] += v;
        __syncthreads();
    }
    if (i < NN) d_rowptr[i] = s[t] - x;
    if (t == 1023) d_bsum[blockIdx.x] = s[1023];
}
__global__ void scanB_kernel(int nblk) {
    if (threadIdx.x == 0 && blockIdx.x == 0) {
        int run = 0;
        for (int b = 0; b < nblk; b++) { int v = d_bsum[b]; d_bsum[b] = run; run += v; }
        d_rowptr[NN] = run;
    }
}
__global__ void scanC_kernel() {
    int i = blockIdx.x * blockDim.x + threadIdx.x;
    if (i < NN) {
        int r = d_rowptr[i] + d_bsum[i >> 10];
        d_rowptr[i] = r;
        d_fill[i] = r;
    }
}

// ---------------- scatter into CSR + per-edge norm float4 ----------------
__global__ void scatter_kernel(const int* __restrict__ src, const int* __restrict__ dst,
                               const float* __restrict__ G) {
    int e = blockIdx.x * blockDim.x + threadIdx.x;
    if (e >= NE) return;
    int d = dst[e];
    int s = src[e];
    int pos = atomicAdd(&d_fill[d], 1);
    d_ssrc[pos] = s;
    float nv[KD];
#pragma unroll
    for (int k = 0; k < KD; k++)
        nv[k] = d_dinv[k * NN + s] * G[k * NE + e] * d_dinv[k * NN + d];
    *(float4*)(d_norm4 + (size_t)pos * 4) = make_float4(nv[0], nv[1], nv[2], nv[3]);
}

// ---------------- GCN layer-1 aggregation ----------------
__global__ void agg1_kernel(const float* __restrict__ g1_b) {
    int w = threadIdx.x >> 5, l = threadIdx.x & 31;
    int n = blockIdx.x * 8 + w;
    if (n >= NN) return;

    float acc[KD][8];
#pragma unroll
    for (int k = 0; k < KD; k++)
#pragma unroll
        for (int j = 0; j < 8; j++) acc[k][j] = 0.0f;

    int beg = d_rowptr[n], end = d_rowptr[n + 1];
    for (int i = beg; i < end; i++) {
        int s = d_ssrc[i];
        float4 nv = *(const float4*)(d_norm4 + (size_t)i * 4);
        float wk[KD] = {nv.x, nv.y, nv.z, nv.w};
        uint4 raw = *((const uint4*)(d_h1 + (size_t)s * H1D) + l);
        __half2* hh = (__half2*)&raw;
        float2 f0 = __half22float2(hh[0]), f1 = __half22float2(hh[1]);
        float2 f2 = __half22float2(hh[2]), f3 = __half22float2(hh[3]);
#pragma unroll
        for (int k = 0; k < KD; k++) {
            float wg = wk[k];
            acc[k][0] = fmaf(wg, f0.x, acc[k][0]); acc[k][1] = fmaf(wg, f0.y, acc[k][1]);
            acc[k][2] = fmaf(wg, f1.x, acc[k][2]); acc[k][3] = fmaf(wg, f1.y, acc[k][3]);
            acc[k][4] = fmaf(wg, f2.x, acc[k][4]); acc[k][5] = fmaf(wg, f2.y, acc[k][5]);
            acc[k][6] = fmaf(wg, f3.x, acc[k][6]); acc[k][7] = fmaf(wg, f3.y, acc[k][7]);
        }
    }
    {
        uint4 raw = *((const uint4*)(d_h1 + (size_t)n * H1D) + l);
        __half2* hh = (__half2*)&raw;
        float2 f0 = __half22float2(hh[0]), f1 = __half22float2(hh[1]);
        float2 f2 = __half22float2(hh[2]), f3 = __half22float2(hh[3]);
#pragma unroll
        for (int k = 0; k < KD; k++) {
            float dv = d_dinv[k * NN + n];
            float wg = dv * dv;
            acc[k][0] = fmaf(wg, f0.x, acc[k][0]); acc[k][1] = fmaf(wg, f0.y, acc[k][1]);
            acc[k][2] = fmaf(wg, f1.x, acc[k][2]); acc[k][3] = fmaf(wg, f1.y, acc[k][3]);
            acc[k][4] = fmaf(wg, f2.x, acc[k][4]); acc[k][5] = fmaf(wg, f2.y, acc[k][5]);
            acc[k][6] = fmaf(wg, f3.x, acc[k][6]); acc[k][7] = fmaf(wg, f3.y, acc[k][7]);
        }
    }
    float4 b0 = ((const float4*)g1_b)[l * 2];
    float4 b1 = ((const float4*)g1_b)[l * 2 + 1];
#pragma unroll
    for (int k = 0; k < KD; k++) {
        uint32_t p0 = h2u(__floats2half2_rn(fmaxf(acc[k][0] + b0.x, 0.f), fmaxf(acc[k][1] + b0.y, 0.f)));
        uint32_t p1 = h2u(__floats2half2_rn(fmaxf(acc[k][2] + b0.z, 0.f), fmaxf(acc[k][3] + b0.w, 0.f)));
        uint32_t p2 = h2u(__floats2half2_rn(fmaxf(acc[k][4] + b1.x, 0.f), fmaxf(acc[k][5] + b1.y, 0.f)));
        uint32_t p3 = h2u(__floats2half2_rn(fmaxf(acc[k][6] + b1.z, 0.f), fmaxf(acc[k][7] + b1.w, 0.f)));
        *((uint4*)(d_z1 + ((size_t)(k * NN + n)) * H1D) + l) = make_uint4(p0, p1, p2, p3);
    }
}

// ---------------- GCN layer-2 aggregation + mean accum (striped partials) -------------
__global__ void agg2_kernel(const float* __restrict__ g2_b) {
    __shared__ float sacc[H2D];
    int t = threadIdx.x;
    int k = blockIdx.y;
    if (t < H2D) sacc[t] = 0.0f;
    __syncthreads();

    int w = t >> 5, l = t & 31;
    int n = blockIdx.x * 8 + w;
    if (n < NN) {
        float a0 = 0.f, a1 = 0.f, a2 = 0.f, a3 = 0.f;
        const __half* h2k = d_h2 + (size_t)k * NN * H2D;

        int beg = d_rowptr[n], end = d_rowptr[n + 1];
        for (int i = beg; i < end; i++) {
            int s = d_ssrc[i];
            float wg = d_norm4[(size_t)i * 4 + k];
            uint2 raw = *((const uint2*)(h2k + (size_t)s * H2D) + l);
            __half2* hh = (__half2*)&raw;
            float2 f0 = __half22float2(hh[0]), f1 = __half22float2(hh[1]);
            a0 = fmaf(wg, f0.x, a0); a1 = fmaf(wg, f0.y, a1);
            a2 = fmaf(wg, f1.x, a2); a3 = fmaf(wg, f1.y, a3);
        }
        {
            float dv = d_dinv[k * NN + n];
            float wg = dv * dv;
            uint2 raw = *((const uint2*)(h2k + (size_t)n * H2D) + l);
            __half2* hh = (__half2*)&raw;
            float2 f0 = __half22float2(hh[0]), f1 = __half22float2(hh[1]);
            a0 = fmaf(wg, f0.x, a0); a1 = fmaf(wg, f0.y, a1);
            a2 = fmaf(wg, f1.x, a2); a3 = fmaf(wg, f1.y, a3);
        }
        float4 b = ((const float4*)g2_b)[l];
        atomicAdd(&sacc[l * 4 + 0], fmaxf(a0 + b.x, 0.f));
        atomicAdd(&sacc[l * 4 + 1], fmaxf(a1 + b.y, 0.f));
        atomicAdd(&sacc[l * 4 + 2], fmaxf(a2 + b.z, 0.f));
        atomicAdd(&sacc[l * 4 + 3], fmaxf(a3 + b.w, 0.f));
    }
    __syncthreads();
    if (t < H2D) atomicAdd(&d_maccP[blockIdx.x & 31][k * H2D + t], sacc[t]);
}

// ---------------- reduce partials ----------------
__global__ void reduce_macc() {
    int i = threadIdx.x;
    float s = 0.0f;
#pragma unroll
    for (int p = 0; p < 32; p++) s += d_maccP[p][i];
    d_macc[i] = s;
}

// ---------------- final descriptors ----------------
__global__ void final_kernel(const float* __restrict__ fc_W, const float* __restrict__ fc_b,
                             float* __restrict__ out) {
    int t = threadIdx.x;
    int k = t >> 5, o = t & 31;
    const float inv = 1.0f / (float)NN;
    float s = fc_b[o];
    for (int d = 0; d < H2D; d++) s = fmaf(d_macc[k * H2D + d] * inv, fc_W[d * ODIM + o], s);
    out[t] = s;
}

// ---------------- launch ----------------
static void* symp(const void* s) {
    void* p = nullptr;
    cudaGetSymbolAddress(&p, s);
    return p;
}

extern "C" void kernel_launch(void* const* d_in, const int* in_sizes, int n_in,
                              void* d_out, int out_size) {
    const float* X     = (const float*)d_in[0];
    const int*   ei    = (const int*)d_in[1];
    const float* Wh    = (const float*)d_in[2];
    const float* W1    = (const float*)d_in[3];
    const float* b1    = (const float*)d_in[4];
    const float* W2    = (const float*)d_in[5];
    const float* b2    = (const float*)d_in[6];
    const float* g1_W  = (const float*)d_in[7];
    const float* g1_b  = (const float*)d_in[8];
    const float* g2_W  = (const float*)d_in[9];
    const float* g2_b  = (const float*)d_in[10];
    const float* fc_W  = (const float*)d_in[11];
    const float* fc_b  = (const float*)d_in[12];

    const int* src = ei;
    const int* dst = ei + NE;

    float* out = (float*)d_out;
    float* G   = out + KD * ODIM;

    __half* p_h0  = (__half*)symp(d_h0);
    __half* p_h1  = (__half*)symp(d_h1);
    __half* p_z1  = (__half*)symp(d_z1);
    __half* p_h2  = (__half*)symp(d_h2);
    __half* p_WhT = (__half*)symp(d_WhT);
    __half* p_g1T = (__half*)symp(d_g1T);
    __half* p_g2T = (__half*)symp(d_g2T);

    const int SMF32 = 3 * (128 * 144 + 128 * 80);   // 86016 -> 2 CTAs/SM
    const int SMF16 = 4 * (128 * 80 + 128 * 80);    // 81920 -> 2 CTAs/SM
    cudaFuncSetAttribute((const void*)gemm_pipe<true, 3>,  cudaFuncAttributeMaxDynamicSharedMemorySize, SMF32);
    cudaFuncSetAttribute((const void*)gemm_pipe<false, 4>, cudaFuncAttributeMaxDynamicSharedMemorySize, SMF16);

    const int PGRID = 296;

    prep_weights<<<(DF * KPAD1 + 255) / 256, 256>>>(Wh, g1_W, g2_W);
    initA_kernel<<<(KD * NN + 255) / 256, 256>>>();
    initB_kernel<<<(NN + 255) / 256, 256>>>();

    // 1. (#4) h0 = fp16(X @ Wh) — R11 config: persistent, scalar-AF32 compute, NS=3
    gemm_pipe<true, 3><<<PGRID, 256, SMF32>>>(X, p_WhT, p_h0, NN, INDIM, KPAD1, DF,
                                              KPAD1 / 32, (NN + 127) / 128, 1);

    // 1b. per-node edge-MLP projections
    pq_kernel<<<(NN * 4 + 255) / 256, 256>>>(W1);

    // 2. edge gates + degree accumulation + dst counts
    edge_gate_kernel<<<(NE + 255) / 256, 256>>>(src, dst, b1, W2, b2, G);

    // 3. dinv
    dinv_kernel<<<(KD * NN + 255) / 256, 256>>>();

    // 4. scan -> rowptr
    int nblk = (NN + 1023) / 1024;
    scanA_kernel<<<nblk, 1024>>>();
    scanB_kernel<<<1, 32>>>(nblk);
    scanC_kernel<<<(NN + 255) / 256, 256>>>();

    // 5. scatter CSR + interleaved norms
    scatter_kernel<<<(NE + 255) / 256, 256>>>(src, dst, G);

    // 6. h1 = fp16(h0 @ g1_W)
    gemm_pipe<false, 4><<<PGRID, 256, SMF16>>>(p_h0, p_g1T, p_h1, NN, DF, DF, H1D,
                                               DF / 32, (NN + 127) / 128, 2);

    // 7. layer-1 aggregation
    agg1_kernel<<<(NN + 7) / 8, 256>>>(g1_b);

    // 8. h2 = fp16(z1 @ g2_W)
    gemm_pipe<false, 4><<<PGRID, 256, SMF16>>>(p_z1, p_g2T, p_h2, KD * NN, H1D, H1D, H2D,
                                               H1D / 32, (KD * NN + 127) / 128, 1);

    // 9. layer-2 aggregation + mean accumulation
    {
        dim3 grid((NN + 7) / 8, KD);
        agg2_kernel<<<grid, 256>>>(g2_b);
    }

    // 9b. reduce partials
    reduce_macc<<<1, KD * H2D>>>();

    // 10. descriptors
    final_kernel<<<1, 128>>>(fc_W, fc_b, out);
}

// round 16
// speedup vs baseline: 1.1481x; 1.0255x over previous
#include <cuda_runtime.h>
#include <cuda_fp16.h>
#include <math.h>
#include <stdint.h>

#define NN    50000
#define NE    300000
#define INDIM 2000
#define DF    128
#define H1D   256
#define H2D   128
#define ODIM  32
#define KD    4
#define KPAD1 2048

// ---------------- scratch (static device globals; no allocation) ----------------
static __device__ __half d_h0[NN * DF];
static __device__ __half d_h1[NN * H1D];
static __device__ __half d_z1[KD * NN * H1D];
static __device__ __half d_h2[NN * KD * H2D];     // node-major interleaved [n][k][128]
static __device__ float  d_pqf[NN * 16];
static __device__ __half d_WhT[DF * KPAD1];
static __device__ __half d_g1T[H1D * DF];
static __device__ __half d_g2T[H2D * H1D];
static __device__ float d_deg[KD * NN];
static __device__ float d_dinv[KD * NN];
static __device__ float d_norm4[NE * 4];          // interleaved [edge][k]
static __device__ int   d_rowptr[NN + 1];
static __device__ int   d_fill[NN];
static __device__ int   d_ssrc[NE];
static __device__ int   d_bsum[64];
static __device__ float d_maccP[32][KD * H2D];
static __device__ float d_macc[KD * H2D];

__device__ __forceinline__ uint32_t h2u(__half2 h) { return *reinterpret_cast<uint32_t*>(&h); }

__device__ __forceinline__ uint32_t smem_u32(const void* p) {
    uint32_t a;
    asm("{ .reg .u64 t; cvta.to.shared.u64 t, %1; cvt.u32.u64 %0, t; }" : "=r"(a) : "l"(p));
    return a;
}
__device__ __forceinline__ void cp_async16(uint32_t saddr, const void* gaddr, uint32_t ssize) {
    asm volatile("cp.async.cg.shared.global [%0], [%1], 16, %2;"
                 :: "r"(saddr), "l"(gaddr), "r"(ssize) : "memory");
}
#define CP_COMMIT() asm volatile("cp.async.commit_group;" ::: "memory")
template <int N>
__device__ __forceinline__ void cp_wait() {
    asm volatile("cp.async.wait_group %0;" :: "n"(N) : "memory");
}
__device__ __forceinline__ void ldmx4(uint32_t* r, uint32_t addr) {
    asm volatile("ldmatrix.sync.aligned.m8n8.x4.shared.b16 {%0,%1,%2,%3}, [%4];"
                 : "=r"(r[0]), "=r"(r[1]), "=r"(r[2]), "=r"(r[3]) : "r"(addr));
}
__device__ __forceinline__ void mma16816(float* d, const uint32_t* a, const uint32_t* b) {
    asm volatile("mma.sync.aligned.m16n8k16.row.col.f32.f16.f16.f32 "
                 "{%0,%1,%2,%3}, {%4,%5,%6,%7}, {%8,%9}, {%0,%1,%2,%3};"
                 : "+f"(d[0]), "+f"(d[1]), "+f"(d[2]), "+f"(d[3])
                 : "r"(a[0]), "r"(a[1]), "r"(a[2]), "r"(a[3]), "r"(b[0]), "r"(b[1]));
}

// ---------------- persistent cp.async HMMA GEMM (R11 config) --------------------------
// kdiv > 0: interleaved output — row r maps to (k=r/kdiv, n=r%kdiv),
//           stored at C + n*(KD*Ntot) + k*Ntot + col.
template <bool AF32, int NS>
__global__ void __launch_bounds__(256, 2) gemm_pipe(const void* __restrict__ Ain,
                                                    const __half* __restrict__ Bt,
                                                    __half* __restrict__ C,
                                                    int M, int Kreal, int KB, int Ntot,
                                                    int NC, int ntm, int ntn, int kdiv) {
    extern __shared__ char sm[];
    const int ASTAGE = AF32 ? (128 * 144) : (128 * 80);
    const int BSTAGE = 128 * 80;
    char* Abase = sm;
    char* Bbase = sm + NS * ASTAGE;

    const int tid = threadIdx.x, lane = tid & 31, w = tid >> 5;
    const int wm = w & 3, wn = w >> 2;
    const int g = lane >> 2, tg = lane & 3;
    const int lr = lane & 7, grp = lane >> 3;
    const int ntiles = ntm * ntn;

    for (int tile = blockIdx.x; tile < ntiles; tile += gridDim.x) {
        const int m0 = (tile % ntm) * 128;
        const int n0 = (tile / ntm) * 128;

        __syncthreads();

        float acc[2][8][4];
#pragma unroll
        for (int i = 0; i < 2; i++)
#pragma unroll
            for (int j = 0; j < 8; j++)
#pragma unroll
                for (int q = 0; q < 4; q++) acc[i][j][q] = 0.0f;

        auto issue_copy = [&](int stage, int c) {
            uint32_t sA = smem_u32(Abase + stage * ASTAGE);
            uint32_t sB = smem_u32(Bbase + stage * BSTAGE);
            if (AF32) {
                const float* A = (const float*)Ain;
#pragma unroll
                for (int t = 0; t < 4; t++) {
                    int idx = tid + t * 256;
                    int row = idx >> 3, c16 = idx & 7;
                    int gr = m0 + row;
                    int gcol = c * 32 + c16 * 4;
                    uint32_t ok = (gr < M && gcol < Kreal) ? 16u : 0u;
                    int grc = (gr < M) ? gr : 0;
                    int gcc = (gcol < Kreal) ? gcol : 0;
                    cp_async16(sA + row * 144 + c16 * 16, A + (size_t)grc * Kreal + gcc, ok);
                }
            } else {
                const __half* A = (const __half*)Ain;
#pragma unroll
                for (int t = 0; t < 2; t++) {
                    int idx = tid + t * 256;
                    int row = idx >> 2, c16 = idx & 3;
                    int gr = m0 + row;
                    uint32_t ok = (gr < M) ? 16u : 0u;
                    int grc = (gr < M) ? gr : 0;
                    cp_async16(sA + row * 80 + c16 * 16, A + (size_t)grc * Kreal + c * 32 + c16 * 8, ok);
                }
            }
#pragma unroll
            for (int t = 0; t < 2; t++) {
                int idx = tid + t * 256;
                int row = idx >> 2, c16 = idx & 3;
                cp_async16(sB + row * 80 + c16 * 16, Bt + (size_t)(n0 + row) * KB + c * 32 + c16 * 8, 16u);
            }
        };

        auto compute = [&](int stage) {
            char* As = Abase + stage * ASTAGE;
            char* Bs = Bbase + stage * BSTAGE;
            uint32_t sAu = smem_u32(As);
            uint32_t sBu = smem_u32(Bs);
#pragma unroll
            for (int ks = 0; ks < 32; ks += 16) {
                uint32_t af[2][4], bf[8][2];
#pragma unroll
                for (int mt = 0; mt < 2; mt++) {
                    if (AF32) {
                        int r0 = wm * 32 + mt * 16 + g;
                        const float2* pA0 = (const float2*)(As + r0 * 144 + (ks + 2 * tg) * 4);
                        const float2* pA1 = (const float2*)(As + (r0 + 8) * 144 + (ks + 2 * tg) * 4);
                        float2 v0 = pA0[0], v1 = pA1[0], v2 = pA0[4], v3 = pA1[4];
                        af[mt][0] = h2u(__floats2half2_rn(v0.x, v0.y));
                        af[mt][1] = h2u(__floats2half2_rn(v1.x, v1.y));
                        af[mt][2] = h2u(__floats2half2_rn(v2.x, v2.y));
                        af[mt][3] = h2u(__floats2half2_rn(v3.x, v3.y));
                    } else {
                        int r = wm * 32 + mt * 16 + (grp & 1) * 8 + lr;
                        int kb = ks + (grp >> 1) * 8;
                        ldmx4(af[mt], sAu + r * 80 + kb * 2);
                    }
                }
#pragma unroll
                for (int np = 0; np < 4; np++) {
                    int r = wn * 64 + np * 16 + (grp >> 1) * 8 + lr;
                    int kb = ks + (grp & 1) * 8;
                    uint32_t t4[4];
                    ldmx4(t4, sBu + r * 80 + kb * 2);
                    bf[np * 2 + 0][0] = t4[0];
                    bf[np * 2 + 0][1] = t4[1];
                    bf[np * 2 + 1][0] = t4[2];
                    bf[np * 2 + 1][1] = t4[3];
                }
#pragma unroll
                for (int mt = 0; mt < 2; mt++)
#pragma unroll
                    for (int nt = 0; nt < 8; nt++)
                        mma16816(acc[mt][nt], af[mt], bf[nt]);
            }
        };

        for (int s = 0; s < NS - 1; s++) {
            if (s < NC) issue_copy(s, s);
            CP_COMMIT();
        }

        for (int c = 0; c < NC; c++) {
            cp_wait<NS - 2>();
            __syncthreads();
            compute(c % NS);
            int cn = c + NS - 1;
            if (cn < NC) issue_copy(cn % NS, cn);
            CP_COMMIT();
        }

        auto rowptr = [&](int r) -> __half* {
            if (kdiv) {
                int kk = r / kdiv, nn = r - kk * kdiv;
                return C + (size_t)nn * (KD * H2D) + (size_t)kk * Ntot;
            }
            return C + (size_t)r * Ntot;
        };
#pragma unroll
        for (int mt = 0; mt < 2; mt++) {
            int r1 = m0 + wm * 32 + mt * 16 + g;
            int r2 = r1 + 8;
            __half* p1 = (r1 < M) ? rowptr(r1) : nullptr;
            __half* p2 = (r2 < M) ? rowptr(r2) : nullptr;
#pragma unroll
            for (int nt = 0; nt < 8; nt++) {
                int col = n0 + wn * 64 + nt * 8 + tg * 2;
                if (p1)
                    *(uint32_t*)(p1 + col) = h2u(__floats2half2_rn(acc[mt][nt][0], acc[mt][nt][1]));
                if (p2)
                    *(uint32_t*)(p2 + col) = h2u(__floats2half2_rn(acc[mt][nt][2], acc[mt][nt][3]));
            }
        }
    }
}

// ---------------- weight prep ----------------
__global__ void prep_weights(const float* __restrict__ Wh, const float* __restrict__ g1W,
                             const float* __restrict__ g2W) {
    int i = blockIdx.x * blockDim.x + threadIdx.x;
    if (i < DF * KPAD1) {
        int n = i / KPAD1, k = i % KPAD1;
        d_WhT[i] = (k < INDIM) ? __float2half(Wh[k * DF + n]) : __half(0.f);
    }
    if (i < H1D * DF) {
        int n = i / DF, k = i % DF;
        d_g1T[i] = __float2half(g1W[k * H1D + n]);
    }
    if (i < H2D * H1D) {
        int n = i / H1D, k = i % H1D;
        d_g2T[i] = __float2half(g2W[k * H2D + n]);
    }
}

// ---------------- init ----------------
__global__ void initA_kernel() {
    int i = blockIdx.x * blockDim.x + threadIdx.x;
    if (i < KD * NN) d_deg[i] = 1.0f;
}
__global__ void initB_kernel() {
    int i = blockIdx.x * blockDim.x + threadIdx.x;
    if (i < NN) d_fill[i] = 0;
    if (i < 32 * KD * H2D) ((float*)d_maccP)[i] = 0.0f;
}

// ---------------- per-node edge-MLP projections: 4 threads/node ----------------
__global__ void pq_kernel(const float* __restrict__ W1) {
    __shared__ float w[DF][16];
    for (int i = threadIdx.x; i < DF * 16; i += 256) {
        int f = i >> 4, o = i & 15;
        float v;
        if (o < 8) { int k = o >> 1, h = o & 1; v = W1[(k * 256 + f) * 2 + h]; }
        else       { int o8 = o - 8; int k = o8 >> 1, h = o8 & 1; v = W1[(k * 256 + 128 + f) * 2 + h]; }
        w[f][o] = v;
    }
    __syncthreads();

    int gid = blockIdx.x * 256 + threadIdx.x;
    int n  = gid >> 2;
    int og = (gid & 3) * 4;
    if (n >= NN) return;

    float a0 = 0.f, a1 = 0.f, a2 = 0.f, a3 = 0.f;
    const uint32_t* hu = (const uint32_t*)(d_h0 + (size_t)n * DF);
#pragma unroll
    for (int j = 0; j < 64; j++) {
        uint32_t raw = hu[j];
        __half2 hx = *reinterpret_cast<__half2*>(&raw);
        float2 x = __half22float2(hx);
        int f = j * 2;
        a0 += x.x * w[f][og + 0] + x.y * w[f + 1][og + 0];
        a1 += x.x * w[f][og + 1] + x.y * w[f + 1][og + 1];
        a2 += x.x * w[f][og + 2] + x.y * w[f + 1][og + 2];
        a3 += x.x * w[f][og + 3] + x.y * w[f + 1][og + 3];
    }
    *(float4*)(d_pqf + (size_t)n * 16 + og) = make_float4(a0, a1, a2, a3);
}

// ---------------- edge gate ----------------
__global__ void edge_gate_kernel(const int* __restrict__ src, const int* __restrict__ dst,
                                 const float* __restrict__ b1, const float* __restrict__ W2,
                                 const float* __restrict__ b2, float* __restrict__ G) {
    int e = blockIdx.x * blockDim.x + threadIdx.x;
    if (e >= NE) return;
    int s = src[e];
    int d = dst[e];
    float4 p0 = *(const float4*)(d_pqf + (size_t)s * 16);
    float4 p1 = *(const float4*)(d_pqf + (size_t)s * 16 + 4);
    float4 q0 = *(const float4*)(d_pqf + (size_t)d * 16 + 8);
    float4 q1 = *(const float4*)(d_pqf + (size_t)d * 16 + 12);
    float pv[8] = {p0.x, p0.y, p0.z, p0.w, p1.x, p1.y, p1.z, p1.w};
    float qv[8] = {q0.x, q0.y, q0.z, q0.w, q1.x, q1.y, q1.z, q1.w};
#pragma unroll
    for (int k = 0; k < KD; k++) {
        float h0v = fmaxf(pv[k * 2 + 0] + qv[k * 2 + 0] + b1[k * 2 + 0], 0.0f);
        float h1v = fmaxf(pv[k * 2 + 1] + qv[k * 2 + 1] + b1[k * 2 + 1], 0.0f);
        float logit = h0v * W2[k * 2 + 0] + h1v * W2[k * 2 + 1] + b2[k];
        float gk = 1.0f / (1.0f + expf(-logit));
        G[k * NE + e] = gk;
        atomicAdd(&d_deg[k * NN + d], gk);
    }
    atomicAdd(&d_fill[d], 1);
}

__global__ void dinv_kernel() {
    int i = blockIdx.x * blockDim.x + threadIdx.x;
    if (i < KD * NN) d_dinv[i] = rsqrtf(d_deg[i]);
}

// ---------------- scan -> rowptr ----------------
__global__ void scanA_kernel() {
    __shared__ int s[1024];
    int t = threadIdx.x;
    int i = blockIdx.x * 1024 + t;
    int x = (i < NN) ? d_fill[i] : 0;
    s[t] = x;
    __syncthreads();
    for (int off = 1; off < 1024; off <<= 1) {
        int v = (t >= off) ? s[t - off] : 0;
        __syncthreads();
        s[t] += v;
        __syncthreads();
    }
    if (i < NN) d_rowptr[i] = s[t] - x;
    if (t == 1023) d_bsum[blockIdx.x] = s[1023];
}
__global__ void scanB_kernel(int nblk) {
    if (threadIdx.x == 0 && blockIdx.x == 0) {
        int run = 0;
        for (int b = 0; b < nblk; b++) { int v = d_bsum[b]; d_bsum[b] = run; run += v; }
        d_rowptr[NN] = run;
    }
}
__global__ void scanC_kernel() {
    int i = blockIdx.x * blockDim.x + threadIdx.x;
    if (i < NN) {
        int r = d_rowptr[i] + d_bsum[i >> 10];
        d_rowptr[i] = r;
        d_fill[i] = r;
    }
}

// ---------------- scatter into CSR + per-edge norm float4 ----------------
__global__ void scatter_kernel(const int* __restrict__ src, const int* __restrict__ dst,
                               const float* __restrict__ G) {
    int e = blockIdx.x * blockDim.x + threadIdx.x;
    if (e >= NE) return;
    int d = dst[e];
    int s = src[e];
    int pos = atomicAdd(&d_fill[d], 1);
    d_ssrc[pos] = s;
    float nv[KD];
#pragma unroll
    for (int k = 0; k < KD; k++)
        nv[k] = d_dinv[k * NN + s] * G[k * NE + e] * d_dinv[k * NN + d];
    *(float4*)(d_norm4 + (size_t)pos * 4) = make_float4(nv[0], nv[1], nv[2], nv[3]);
}

// ---------------- GCN layer-1 aggregation ----------------
__global__ void agg1_kernel(const float* __restrict__ g1_b) {
    int w = threadIdx.x >> 5, l = threadIdx.x & 31;
    int n = blockIdx.x * 8 + w;
    if (n >= NN) return;

    float acc[KD][8];
#pragma unroll
    for (int k = 0; k < KD; k++)
#pragma unroll
        for (int j = 0; j < 8; j++) acc[k][j] = 0.0f;

    int beg = d_rowptr[n], end = d_rowptr[n + 1];
    for (int i = beg; i < end; i++) {
        int s = d_ssrc[i];
        float4 nv = *(const float4*)(d_norm4 + (size_t)i * 4);
        float wk[KD] = {nv.x, nv.y, nv.z, nv.w};
        uint4 raw = *((const uint4*)(d_h1 + (size_t)s * H1D) + l);
        __half2* hh = (__half2*)&raw;
        float2 f0 = __half22float2(hh[0]), f1 = __half22float2(hh[1]);
        float2 f2 = __half22float2(hh[2]), f3 = __half22float2(hh[3]);
#pragma unroll
        for (int k = 0; k < KD; k++) {
            float wg = wk[k];
            acc[k][0] = fmaf(wg, f0.x, acc[k][0]); acc[k][1] = fmaf(wg, f0.y, acc[k][1]);
            acc[k][2] = fmaf(wg, f1.x, acc[k][2]); acc[k][3] = fmaf(wg, f1.y, acc[k][3]);
            acc[k][4] = fmaf(wg, f2.x, acc[k][4]); acc[k][5] = fmaf(wg, f2.y, acc[k][5]);
            acc[k][6] = fmaf(wg, f3.x, acc[k][6]); acc[k][7] = fmaf(wg, f3.y, acc[k][7]);
        }
    }
    {
        uint4 raw = *((const uint4*)(d_h1 + (size_t)n * H1D) + l);
        __half2* hh = (__half2*)&raw;
        float2 f0 = __half22float2(hh[0]), f1 = __half22float2(hh[1]);
        float2 f2 = __half22float2(hh[2]), f3 = __half22float2(hh[3]);
#pragma unroll
        for (int k = 0; k < KD; k++) {
            float dv = d_dinv[k * NN + n];
            float wg = dv * dv;
            acc[k][0] = fmaf(wg, f0.x, acc[k][0]); acc[k][1] = fmaf(wg, f0.y, acc[k][1]);
            acc[k][2] = fmaf(wg, f1.x, acc[k][2]); acc[k][3] = fmaf(wg, f1.y, acc[k][3]);
            acc[k][4] = fmaf(wg, f2.x, acc[k][4]); acc[k][5] = fmaf(wg, f2.y, acc[k][5]);
            acc[k][6] = fmaf(wg, f3.x, acc[k][6]); acc[k][7] = fmaf(wg, f3.y, acc[k][7]);
        }
    }
    float4 b0 = ((const float4*)g1_b)[l * 2];
    float4 b1 = ((const float4*)g1_b)[l * 2 + 1];
#pragma unroll
    for (int k = 0; k < KD; k++) {
        uint32_t p0 = h2u(__floats2half2_rn(fmaxf(acc[k][0] + b0.x, 0.f), fmaxf(acc[k][1] + b0.y, 0.f)));
        uint32_t p1 = h2u(__floats2half2_rn(fmaxf(acc[k][2] + b0.z, 0.f), fmaxf(acc[k][3] + b0.w, 0.f)));
        uint32_t p2 = h2u(__floats2half2_rn(fmaxf(acc[k][4] + b1.x, 0.f), fmaxf(acc[k][5] + b1.y, 0.f)));
        uint32_t p3 = h2u(__floats2half2_rn(fmaxf(acc[k][6] + b1.z, 0.f), fmaxf(acc[k][7] + b1.w, 0.f)));
        *((uint4*)(d_z1 + ((size_t)(k * NN + n)) * H1D) + l) = make_uint4(p0, p1, p2, p3);
    }
}

// ---------------- fused GCN layer-2 aggregation (ALL k in one pass) + mean accum ------
__global__ void agg2_fused_kernel(const float* __restrict__ g2_b) {
    __shared__ float sacc[KD * H2D];
    int t = threadIdx.x;
    for (int i = t; i < KD * H2D; i += 256) sacc[i] = 0.0f;
    __syncthreads();

    int w = t >> 5, l = t & 31;
    int n = blockIdx.x * 8 + w;
    if (n < NN) {
        float acc[KD][4];
#pragma unroll
        for (int k = 0; k < KD; k++)
#pragma unroll
            for (int j = 0; j < 4; j++) acc[k][j] = 0.0f;

        int beg = d_rowptr[n], end = d_rowptr[n + 1];
        for (int i = beg; i < end; i++) {
            int s = d_ssrc[i];
            float4 nv = *(const float4*)(d_norm4 + (size_t)i * 4);
            float wk[KD] = {nv.x, nv.y, nv.z, nv.w};
            const __half* hsrc = d_h2 + (size_t)s * (KD * H2D);
#pragma unroll
            for (int k = 0; k < KD; k++) {
                uint2 raw = *((const uint2*)(hsrc + k * H2D) + l);
                __half2* hh = (__half2*)&raw;
                float2 f0 = __half22float2(hh[0]), f1 = __half22float2(hh[1]);
                float wg = wk[k];
                acc[k][0] = fmaf(wg, f0.x, acc[k][0]); acc[k][1] = fmaf(wg, f0.y, acc[k][1]);
                acc[k][2] = fmaf(wg, f1.x, acc[k][2]); acc[k][3] = fmaf(wg, f1.y, acc[k][3]);
            }
        }
        {
            const __half* hsrc = d_h2 + (size_t)n * (KD * H2D);
#pragma unroll
            for (int k = 0; k < KD; k++) {
                float dv = d_dinv[k * NN + n];
                float wg = dv * dv;
                uint2 raw = *((const uint2*)(hsrc + k * H2D) + l);
                __half2* hh = (__half2*)&raw;
                float2 f0 = __half22float2(hh[0]), f1 = __half22float2(hh[1]);
                acc[k][0] = fmaf(wg, f0.x, acc[k][0]); acc[k][1] = fmaf(wg, f0.y, acc[k][1]);
                acc[k][2] = fmaf(wg, f1.x, acc[k][2]); acc[k][3] = fmaf(wg, f1.y, acc[k][3]);
            }
        }
        float4 b = ((const float4*)g2_b)[l];
#pragma unroll
        for (int k = 0; k < KD; k++) {
            atomicAdd(&sacc[k * H2D + l * 4 + 0], fmaxf(acc[k][0] + b.x, 0.f));
            atomicAdd(&sacc[k * H2D + l * 4 + 1], fmaxf(acc[k][1] + b.y, 0.f));
            atomicAdd(&sacc[k * H2D + l * 4 + 2], fmaxf(acc[k][2] + b.z, 0.f));
            atomicAdd(&sacc[k * H2D + l * 4 + 3], fmaxf(acc[k][3] + b.w, 0.f));
        }
    }
    __syncthreads();
    for (int i = t; i < KD * H2D; i += 256)
        atomicAdd(&d_maccP[blockIdx.x & 31][i], sacc[i]);
}

// ---------------- reduce partials ----------------
__global__ void reduce_macc() {
    int i = threadIdx.x;
    float s = 0.0f;
#pragma unroll
    for (int p = 0; p < 32; p++) s += d_maccP[p][i];
    d_macc[i] = s;
}

// ---------------- final descriptors ----------------
__global__ void final_kernel(const float* __restrict__ fc_W, const float* __restrict__ fc_b,
                             float* __restrict__ out) {
    int t = threadIdx.x;
    int k = t >> 5, o = t & 31;
    const float inv = 1.0f / (float)NN;
    float s = fc_b[o];
    for (int d = 0; d < H2D; d++) s = fmaf(d_macc[k * H2D + d] * inv, fc_W[d * ODIM + o], s);
    out[t] = s;
}

// ---------------- launch ----------------
static void* symp(const void* s) {
    void* p = nullptr;
    cudaGetSymbolAddress(&p, s);
    return p;
}

extern "C" void kernel_launch(void* const* d_in, const int* in_sizes, int n_in,
                              void* d_out, int out_size) {
    const float* X     = (const float*)d_in[0];
    const int*   ei    = (const int*)d_in[1];
    const float* Wh    = (const float*)d_in[2];
    const float* W1    = (const float*)d_in[3];
    const float* b1    = (const float*)d_in[4];
    const float* W2    = (const float*)d_in[5];
    const float* b2    = (const float*)d_in[6];
    const float* g1_W  = (const float*)d_in[7];
    const float* g1_b  = (const float*)d_in[8];
    const float* g2_W  = (const float*)d_in[9];
    const float* g2_b  = (const float*)d_in[10];
    const float* fc_W  = (const float*)d_in[11];
    const float* fc_b  = (const float*)d_in[12];

    const int* src = ei;
    const int* dst = ei + NE;

    float* out = (float*)d_out;
    float* G   = out + KD * ODIM;

    __half* p_h0  = (__half*)symp(d_h0);
    __half* p_h1  = (__half*)symp(d_h1);
    __half* p_z1  = (__half*)symp(d_z1);
    __half* p_h2  = (__half*)symp(d_h2);
    __half* p_WhT = (__half*)symp(d_WhT);
    __half* p_g1T = (__half*)symp(d_g1T);
    __half* p_g2T = (__half*)symp(d_g2T);

    const int SMF32 = 3 * (128 * 144 + 128 * 80);   // 86016 -> 2 CTAs/SM
    const int SMF16 = 4 * (128 * 80 + 128 * 80);    // 81920 -> 2 CTAs/SM
    cudaFuncSetAttribute((const void*)gemm_pipe<true, 3>,  cudaFuncAttributeMaxDynamicSharedMemorySize, SMF32);
    cudaFuncSetAttribute((const void*)gemm_pipe<false, 4>, cudaFuncAttributeMaxDynamicSharedMemorySize, SMF16);

    const int PGRID = 296;

    prep_weights<<<(DF * KPAD1 + 255) / 256, 256>>>(Wh, g1_W, g2_W);
    initA_kernel<<<(KD * NN + 255) / 256, 256>>>();
    initB_kernel<<<(NN + 255) / 256, 256>>>();

    // 1. (#4) h0 = fp16(X @ Wh)
    gemm_pipe<true, 3><<<PGRID, 256, SMF32>>>(X, p_WhT, p_h0, NN, INDIM, KPAD1, DF,
                                              KPAD1 / 32, (NN + 127) / 128, 1, 0);

    // 1b. per-node edge-MLP projections
    pq_kernel<<<(NN * 4 + 255) / 256, 256>>>(W1);

    // 2. edge gates + degree accumulation + dst counts
    edge_gate_kernel<<<(NE + 255) / 256, 256>>>(src, dst, b1, W2, b2, G);

    // 3. dinv
    dinv_kernel<<<(KD * NN + 255) / 256, 256>>>();

    // 4. scan -> rowptr
    int nblk = (NN + 1023) / 1024;
    scanA_kernel<<<nblk, 1024>>>();
    scanB_kernel<<<1, 32>>>(nblk);
    scanC_kernel<<<(NN + 255) / 256, 256>>>();

    // 5. scatter CSR + interleaved norms
    scatter_kernel<<<(NE + 255) / 256, 256>>>(src, dst, G);

    // 6. h1 = fp16(h0 @ g1_W)
    gemm_pipe<false, 4><<<PGRID, 256, SMF16>>>(p_h0, p_g1T, p_h1, NN, DF, DF, H1D,
                                               DF / 32, (NN + 127) / 128, 2, 0);

    // 7. layer-1 aggregation
    agg1_kernel<<<(NN + 7) / 8, 256>>>(g1_b);

    // 8. h2 = fp16(z1 @ g2_W), written node-major interleaved [n][k][128]
    gemm_pipe<false, 4><<<PGRID, 256, SMF16>>>(p_z1, p_g2T, p_h2, KD * NN, H1D, H1D, H2D,
                                               H1D / 32, (KD * NN + 127) / 128, 1, NN);

    // 9. fused layer-2 aggregation (all k, one edge sweep) + mean accumulation
    agg2_fused_kernel<<<(NN + 7) / 8, 256>>>(g2_b);

    // 9b. reduce partials
    reduce_macc<<<1, KD * H2D>>>();

    // 10. descriptors
    final_kernel<<<1, 128>>>(fc_W, fc_b, out);
}